// round 1
// baseline (speedup 1.0000x reference)
#include <cuda_runtime.h>

#define NN 100000
#define EE 1600000
#define F1 128
#define FH 128
#define FO 64

// ---------------- scratch (device globals; no allocations allowed) ----------
__device__ float g_y[(size_t)NN * FH];   // x @ w1_rel
__device__ float g_z[(size_t)NN * FH];   // x @ w1_root
__device__ float g_h[(size_t)NN * FH];   // hidden after relu
__device__ float g_p[(size_t)NN * FO];   // h @ w2_rel
__device__ float g_q[(size_t)NN * FO];   // h @ w2_root
__device__ int   g_rowptr[NN + 1];
__device__ int   g_cnt[NN];
__device__ int   g_cursor[NN];
__device__ int   g_col[EE];              // src node per CSR slot (dst-indexed)
__device__ int   g_is64;

// ---------------- dtype detection: int64 vs int32 edge_index ----------------
// If edge_index is int64 (values < 2^31, nonneg), every odd 32-bit word is 0.
__global__ void k_detect(const int* __restrict__ ebuf) {
    if (threadIdx.x == 0) {
        int is64 = 1;
        for (int i = 1; i < 1024; i += 2) {
            if (ebuf[i] != 0) { is64 = 0; break; }
        }
        g_is64 = is64;
    }
}

__global__ void k_zero_cnt() {
    int i = blockIdx.x * blockDim.x + threadIdx.x;
    if (i < NN) g_cnt[i] = 0;
}

__device__ __forceinline__ int edge_at(const void* ebuf, int is64, long long idx) {
    if (is64) return (int)((const long long*)ebuf)[idx];
    return ((const int*)ebuf)[idx];
}

__global__ void k_count(const void* __restrict__ ebuf) {
    int e = blockIdx.x * blockDim.x + threadIdx.x;
    if (e >= EE) return;
    int is64 = g_is64;
    int dst = edge_at(ebuf, is64, (long long)EE + e);
    atomicAdd(&g_cnt[dst], 1);
}

// single-block exclusive scan over g_cnt -> g_rowptr / g_cursor
__global__ void k_scan() {
    __shared__ int warp_sums[32];
    __shared__ int s_carry;
    int t = threadIdx.x;
    if (t == 0) s_carry = 0;
    __syncthreads();
    const int nChunks = (NN + 1023) / 1024;
    for (int c = 0; c < nChunks; c++) {
        int idx = c * 1024 + t;
        int v = (idx < NN) ? g_cnt[idx] : 0;
        // warp inclusive scan
        int x = v;
        #pragma unroll
        for (int o = 1; o < 32; o <<= 1) {
            int y = __shfl_up_sync(0xFFFFFFFFu, x, o);
            if ((t & 31) >= o) x += y;
        }
        if ((t & 31) == 31) warp_sums[t >> 5] = x;
        __syncthreads();
        if (t < 32) {
            int w = warp_sums[t];
            #pragma unroll
            for (int o = 1; o < 32; o <<= 1) {
                int y = __shfl_up_sync(0xFFFFFFFFu, w, o);
                if (t >= o) w += y;
            }
            warp_sums[t] = w;
        }
        __syncthreads();
        int wprefix = (t >= 32) ? warp_sums[(t >> 5) - 1] : 0;
        int incl = x + wprefix;
        int excl = incl - v + s_carry;
        if (idx < NN) { g_rowptr[idx] = excl; g_cursor[idx] = excl; }
        __syncthreads();
        if (t == 1023) s_carry += incl;   // incl at t=1023 == chunk total
        __syncthreads();
    }
    if (t == 0) g_rowptr[NN] = s_carry;
}

__global__ void k_fill(const void* __restrict__ ebuf) {
    int e = blockIdx.x * blockDim.x + threadIdx.x;
    if (e >= EE) return;
    int is64 = g_is64;
    int src = edge_at(ebuf, is64, e);
    int dst = edge_at(ebuf, is64, (long long)EE + e);
    int pos = atomicAdd(&g_cursor[dst], 1);
    g_col[pos] = src;
}

// ---------------- SGEMM: C[nrows, BN] = A[nrows, 128] * W[128, BN] ----------
template <int BN>
__global__ __launch_bounds__(256) void k_gemm(const float* __restrict__ A,
                                              const float* __restrict__ W,
                                              float* __restrict__ C,
                                              int nrows) {
    constexpr int BM = 128, BK = 16;
    constexpr int TM = 8;
    constexpr int TN = BN / 16;           // 8 for BN=128, 4 for BN=64
    __shared__ __align__(16) float As[BK][BM + 4];
    __shared__ __align__(16) float Ws[BK][BN];

    int tid = threadIdx.x;
    int tr = tid >> 4;                    // 0..15
    int tc = tid & 15;                    // 0..15
    int rowBase = blockIdx.x * BM;

    float acc[TM][TN];
    #pragma unroll
    for (int i = 0; i < TM; i++)
        #pragma unroll
        for (int j = 0; j < TN; j++) acc[i][j] = 0.f;

    for (int k0 = 0; k0 < 128; k0 += BK) {
        // load A tile (BM x BK), stored transposed As[k][m]
        #pragma unroll
        for (int i = 0; i < 2; i++) {
            int s = tid + i * 256;        // 512 float4 slots
            int r = s >> 2;               // row 0..127
            int kq = (s & 3) << 2;        // 0,4,8,12
            float4 v = make_float4(0.f, 0.f, 0.f, 0.f);
            int gr = rowBase + r;
            if (gr < nrows) v = *(const float4*)&A[(size_t)gr * 128 + k0 + kq];
            As[kq + 0][r] = v.x; As[kq + 1][r] = v.y;
            As[kq + 2][r] = v.z; As[kq + 3][r] = v.w;
        }
        // load W tile (BK x BN), row-major
        constexpr int WSLOTS = BK * BN / 4;
        #pragma unroll
        for (int i = 0; i < (WSLOTS + 255) / 256; i++) {
            int s = tid + i * 256;
            if (s < WSLOTS) {
                int r = s / (BN / 4);
                int cq = (s % (BN / 4)) * 4;
                *(float4*)&Ws[r][cq] = *(const float4*)&W[(size_t)(k0 + r) * BN + cq];
            }
        }
        __syncthreads();
        #pragma unroll
        for (int k = 0; k < BK; k++) {
            float a[TM], b[TN];
            const float4* ap = (const float4*)&As[k][tr * TM];
            float4 a0 = ap[0], a1 = ap[1];
            a[0] = a0.x; a[1] = a0.y; a[2] = a0.z; a[3] = a0.w;
            a[4] = a1.x; a[5] = a1.y; a[6] = a1.z; a[7] = a1.w;
            const float4* bp = (const float4*)&Ws[k][tc * TN];
            #pragma unroll
            for (int j = 0; j < TN / 4; j++) {
                float4 bv = bp[j];
                b[4 * j + 0] = bv.x; b[4 * j + 1] = bv.y;
                b[4 * j + 2] = bv.z; b[4 * j + 3] = bv.w;
            }
            #pragma unroll
            for (int i = 0; i < TM; i++)
                #pragma unroll
                for (int j = 0; j < TN; j++)
                    acc[i][j] += a[i] * b[j];
        }
        __syncthreads();
    }
    #pragma unroll
    for (int i = 0; i < TM; i++) {
        int gr = rowBase + tr * TM + i;
        if (gr < nrows) {
            #pragma unroll
            for (int j = 0; j < TN; j += 4) {
                *(float4*)&C[(size_t)gr * BN + tc * TN + j] =
                    make_float4(acc[i][j], acc[i][j + 1], acc[i][j + 2], acc[i][j + 3]);
            }
        }
    }
}

// ---------------- aggregation layer 1: h = relu(sum y[src] + b1 + z) --------
__global__ __launch_bounds__(256) void k_agg1(const float* __restrict__ b1) {
    int node = blockIdx.x * (blockDim.x / 32) + (threadIdx.x >> 5);
    if (node >= NN) return;
    int lane = threadIdx.x & 31;
    int beg = g_rowptr[node], end = g_rowptr[node + 1];
    float4 bv = *(const float4*)&b1[lane * 4];
    float4 zv = *(const float4*)&g_z[(size_t)node * FH + lane * 4];
    float4 acc = make_float4(bv.x + zv.x, bv.y + zv.y, bv.z + zv.z, bv.w + zv.w);
    for (int p = beg; p < end; p++) {
        int s = g_col[p];
        float4 v = *(const float4*)&g_y[(size_t)s * FH + lane * 4];
        acc.x += v.x; acc.y += v.y; acc.z += v.z; acc.w += v.w;
    }
    acc.x = fmaxf(acc.x, 0.f); acc.y = fmaxf(acc.y, 0.f);
    acc.z = fmaxf(acc.z, 0.f); acc.w = fmaxf(acc.w, 0.f);
    *(float4*)&g_h[(size_t)node * FH + lane * 4] = acc;
}

// ---------------- aggregation layer 2: out = sum p[src] + b2 + q ------------
__global__ __launch_bounds__(256) void k_agg2(const float* __restrict__ b2,
                                              float* __restrict__ out) {
    int node = blockIdx.x * (blockDim.x / 32) + (threadIdx.x >> 5);
    if (node >= NN) return;
    int lane = threadIdx.x & 31;
    int beg = g_rowptr[node], end = g_rowptr[node + 1];
    float2 bv = *(const float2*)&b2[lane * 2];
    float2 qv = *(const float2*)&g_q[(size_t)node * FO + lane * 2];
    float2 acc = make_float2(bv.x + qv.x, bv.y + qv.y);
    for (int p = beg; p < end; p++) {
        int s = g_col[p];
        float2 v = *(const float2*)&g_p[(size_t)s * FO + lane * 2];
        acc.x += v.x; acc.y += v.y;
    }
    *(float2*)&out[(size_t)node * FO + lane * 2] = acc;
}

// ---------------- launch -----------------------------------------------------
extern "C" void kernel_launch(void* const* d_in, const int* in_sizes, int n_in,
                              void* d_out, int out_size) {
    const float* x   = (const float*)d_in[0];
    const void*  ei  = d_in[1];
    const float* w1r = (const float*)d_in[2];
    const float* b1  = (const float*)d_in[3];
    const float* w1o = (const float*)d_in[4];
    const float* w2r = (const float*)d_in[5];
    const float* b2  = (const float*)d_in[6];
    const float* w2o = (const float*)d_in[7];
    float* out = (float*)d_out;

    float *yp, *zp, *hp, *pp, *qp;
    cudaGetSymbolAddress((void**)&yp, g_y);
    cudaGetSymbolAddress((void**)&zp, g_z);
    cudaGetSymbolAddress((void**)&hp, g_h);
    cudaGetSymbolAddress((void**)&pp, g_p);
    cudaGetSymbolAddress((void**)&qp, g_q);

    const int EB = (EE + 255) / 256;
    const int NB = (NN + 255) / 256;
    const int GB = (NN + 127) / 128;     // gemm blocks
    const int AB = (NN + 7) / 8;         // agg blocks (8 warps/block)

    // CSR build
    k_detect<<<1, 32>>>((const int*)ei);
    k_zero_cnt<<<NB, 256>>>();
    k_count<<<EB, 256>>>(ei);
    k_scan<<<1, 1024>>>();
    k_fill<<<EB, 256>>>(ei);

    // layer 1
    k_gemm<128><<<GB, 256>>>(x, w1r, yp, NN);
    k_gemm<128><<<GB, 256>>>(x, w1o, zp, NN);
    k_agg1<<<AB, 256>>>(b1);

    // layer 2
    k_gemm<64><<<GB, 256>>>(hp, w2r, pp, NN);
    k_gemm<64><<<GB, 256>>>(hp, w2o, qp, NN);
    k_agg2<<<AB, 256>>>(b2, out);
}

// round 3
// speedup vs baseline: 1.2552x; 1.2552x over previous
#include <cuda_runtime.h>

#define NN 100000
#define EE 1600000
#define F1 128
#define FH 128
#define FO 64
#define NBLK_SCAN ((NN + 1023) / 1024)   // 98

// ---------------- scratch (device globals; no allocations allowed) ----------
__device__ float g_y[(size_t)NN * FH];   // x @ w1_rel
__device__ float g_z[(size_t)NN * FH];   // x @ w1_root
__device__ float g_h[(size_t)NN * FH];   // hidden after relu
__device__ float g_p[(size_t)NN * FO];   // h @ w2_rel
__device__ float g_q[(size_t)NN * FO];   // h @ w2_root
__device__ int   g_rowptr[NN + 1];
__device__ int   g_cnt[NN];
__device__ int   g_cursor[NN];
__device__ int   g_col[EE];              // src node per CSR slot (dst-indexed)
__device__ int   g_is64;
__device__ int   g_bsum[NBLK_SCAN + 32];
__device__ int   g_bsumx[NBLK_SCAN + 32];

// ---------------- dtype detection: int64 vs int32 edge_index ----------------
// If edge_index is int64 (values in [0,2^31)), every odd 32-bit word is 0.
__global__ void k_detect(const int* __restrict__ ebuf) {
    __shared__ int bad;
    if (threadIdx.x == 0) bad = 0;
    __syncthreads();
    for (int i = threadIdx.x; i < 2048; i += blockDim.x)
        if (ebuf[2 * i + 1] != 0) bad = 1;
    __syncthreads();
    if (threadIdx.x == 0) g_is64 = bad ? 0 : 1;
}

__global__ void k_zero_cnt() {
    int i = blockIdx.x * blockDim.x + threadIdx.x;
    if (i < NN) g_cnt[i] = 0;
}

__device__ __forceinline__ int edge_at(const void* ebuf, int is64, long long idx) {
    if (is64) return (int)((const long long*)ebuf)[idx];
    return ((const int*)ebuf)[idx];
}

__global__ void k_count(const void* __restrict__ ebuf) {
    int e = blockIdx.x * blockDim.x + threadIdx.x;
    if (e >= EE) return;
    int is64 = g_is64;
    int dst = edge_at(ebuf, is64, (long long)EE + e);
    atomicAdd(&g_cnt[dst], 1);
}

// ---------------- multi-block exclusive scan (3 phases) ---------------------
__global__ __launch_bounds__(1024) void k_scan1() {
    __shared__ int ws[32];
    int t = threadIdx.x;
    int idx = blockIdx.x * 1024 + t;
    int v = (idx < NN) ? g_cnt[idx] : 0;
    int x = v;
    #pragma unroll
    for (int o = 1; o < 32; o <<= 1) {
        int y = __shfl_up_sync(0xFFFFFFFFu, x, o);
        if ((t & 31) >= o) x += y;
    }
    if ((t & 31) == 31) ws[t >> 5] = x;
    __syncthreads();
    if (t < 32) {
        int w = ws[t];
        #pragma unroll
        for (int o = 1; o < 32; o <<= 1) {
            int y = __shfl_up_sync(0xFFFFFFFFu, w, o);
            if (t >= o) w += y;
        }
        ws[t] = w;
    }
    __syncthreads();
    int prefix = (t >= 32) ? ws[(t >> 5) - 1] : 0;
    int incl = x + prefix;
    if (idx < NN) g_rowptr[idx] = incl - v;        // block-local exclusive
    if (t == 1023) g_bsum[blockIdx.x] = incl;      // block total
}

__global__ __launch_bounds__(128) void k_scan2() {
    int t = threadIdx.x;
    int v = (t < NBLK_SCAN) ? g_bsum[t] : 0;
    int x = v;
    #pragma unroll
    for (int o = 1; o < 32; o <<= 1) {
        int y = __shfl_up_sync(0xFFFFFFFFu, x, o);
        if ((t & 31) >= o) x += y;
    }
    __shared__ int ws[4];
    if ((t & 31) == 31) ws[t >> 5] = x;
    __syncthreads();
    if (t < 4) {
        int w = ws[t];
        #pragma unroll
        for (int o = 1; o < 4; o <<= 1) {
            int y = __shfl_up_sync(0xFu, w, o);
            if (t >= o) w += y;
        }
        ws[t] = w;
    }
    __syncthreads();
    int prefix = (t >= 32) ? ws[(t >> 5) - 1] : 0;
    if (t < NBLK_SCAN) g_bsumx[t] = x + prefix - v;
}

__global__ __launch_bounds__(1024) void k_scan3() {
    int t = threadIdx.x;
    int idx = blockIdx.x * 1024 + t;
    int off = g_bsumx[blockIdx.x];
    if (idx < NN) {
        int r = g_rowptr[idx] + off;
        g_rowptr[idx] = r;
        g_cursor[idx] = r;
    }
    if (idx == 0) g_rowptr[NN] = EE;
}

__global__ void k_fill(const void* __restrict__ ebuf) {
    int e = blockIdx.x * blockDim.x + threadIdx.x;
    if (e >= EE) return;
    int is64 = g_is64;
    int src = edge_at(ebuf, is64, e);
    int dst = edge_at(ebuf, is64, (long long)EE + e);
    int pos = atomicAdd(&g_cursor[dst], 1);
    g_col[pos] = src;
}

// ---------------- tf32 tensor-core GEMM (3xTF32: fp32-class accuracy) -------
__device__ __forceinline__ unsigned f2tf(float x) {
    unsigned r;
    asm("cvt.rna.tf32.f32 %0, %1;" : "=r"(r) : "f"(x));
    return r;
}

__device__ __forceinline__ void mma_tf32(float* c, const unsigned* a, const unsigned* b) {
    asm volatile(
        "mma.sync.aligned.m16n8k8.row.col.f32.tf32.tf32.f32 "
        "{%0,%1,%2,%3}, {%4,%5,%6,%7}, {%8,%9}, {%0,%1,%2,%3};\n"
        : "+f"(c[0]), "+f"(c[1]), "+f"(c[2]), "+f"(c[3])
        : "r"(a[0]), "r"(a[1]), "r"(a[2]), "r"(a[3]), "r"(b[0]), "r"(b[1]));
}

// C[nrows,128] = A[nrows,128] * B[128,128]
// split=0: B = W (128x128), W/C chosen by blockIdx.y (two independent GEMMs).
// split=1: B = [W0 | W1] (each 128x64), outputs to C0 / C1.
#define BM 128
#define BKK 16
#define ASTR 132
#define BSTR 132

__global__ __launch_bounds__(256) void k_gemm_tf32(
    const float* __restrict__ A,
    const float* __restrict__ W0, const float* __restrict__ W1,
    float* __restrict__ C0, float* __restrict__ C1,
    int nrows, int split)
{
    __shared__ float Ah[BKK][ASTR], Al[BKK][ASTR];
    __shared__ float Bh[BKK][BSTR], Bl[BKK][BSTR];

    int tid = threadIdx.x;
    int wid = tid >> 5, lane = tid & 31;
    int g = lane >> 2, q = lane & 3;          // groupID, threadInGroup
    int warpRow = (wid >> 2) * 64;            // 2 warps over M
    int warpCol = (wid & 3) * 32;             // 4 warps over N
    int rowBase = blockIdx.x * BM;

    const float* Wsel = (blockIdx.y == 0) ? W0 : W1;
    float* Csel = (blockIdx.y == 0) ? C0 : C1;

    float acc[4][4][4];
    #pragma unroll
    for (int i = 0; i < 4; i++)
        #pragma unroll
        for (int j = 0; j < 4; j++)
            #pragma unroll
            for (int r = 0; r < 4; r++) acc[i][j][r] = 0.f;

    for (int k0 = 0; k0 < 128; k0 += BKK) {
        // A tile: 128 rows x 16 k, 512 float4 slots, 2 per thread; store hi/lo transposed
        #pragma unroll
        for (int it = 0; it < 2; it++) {
            int s = tid + it * 256;
            int r = s >> 2;
            int kq = (s & 3) << 2;
            float4 v = make_float4(0.f, 0.f, 0.f, 0.f);
            int gr = rowBase + r;
            if (gr < nrows) v = *(const float4*)&A[(size_t)gr * 128 + k0 + kq];
            float vv[4] = {v.x, v.y, v.z, v.w};
            #pragma unroll
            for (int c = 0; c < 4; c++) {
                unsigned hi = f2tf(vv[c]);
                float lo = vv[c] - __uint_as_float(hi);
                Ah[kq + c][r] = __uint_as_float(hi);
                Al[kq + c][r] = __uint_as_float(f2tf(lo));
            }
        }
        // B tile: 16 k-rows x 128 cols, 512 float4 slots, 2 per thread
        #pragma unroll
        for (int it = 0; it < 2; it++) {
            int s = tid + it * 256;
            int r = s >> 5;                    // k row 0..15
            int cq = (s & 31) << 2;            // col 0..124
            float4 v;
            if (!split) {
                v = *(const float4*)&Wsel[(size_t)(k0 + r) * 128 + cq];
            } else {
                if (cq < 64) v = *(const float4*)&W0[(size_t)(k0 + r) * 64 + cq];
                else         v = *(const float4*)&W1[(size_t)(k0 + r) * 64 + cq - 64];
            }
            float vv[4] = {v.x, v.y, v.z, v.w};
            #pragma unroll
            for (int c = 0; c < 4; c++) {
                unsigned hi = f2tf(vv[c]);
                float lo = vv[c] - __uint_as_float(hi);
                Bh[r][cq + c] = __uint_as_float(hi);
                Bl[r][cq + c] = __uint_as_float(f2tf(lo));
            }
        }
        __syncthreads();

        #pragma unroll
        for (int k8 = 0; k8 < BKK / 8; k8++) {
            int kb = k8 * 8;
            unsigned ah[4][4], al[4][4], bh[4][2], bl[4][2];
            #pragma unroll
            for (int i = 0; i < 4; i++) {
                int r0 = warpRow + i * 16 + g;
                ah[i][0] = __float_as_uint(Ah[kb + q][r0]);
                ah[i][1] = __float_as_uint(Ah[kb + q][r0 + 8]);
                ah[i][2] = __float_as_uint(Ah[kb + q + 4][r0]);
                ah[i][3] = __float_as_uint(Ah[kb + q + 4][r0 + 8]);
                al[i][0] = __float_as_uint(Al[kb + q][r0]);
                al[i][1] = __float_as_uint(Al[kb + q][r0 + 8]);
                al[i][2] = __float_as_uint(Al[kb + q + 4][r0]);
                al[i][3] = __float_as_uint(Al[kb + q + 4][r0 + 8]);
            }
            #pragma unroll
            for (int j = 0; j < 4; j++) {
                int c0 = warpCol + j * 8 + g;
                bh[j][0] = __float_as_uint(Bh[kb + q][c0]);
                bh[j][1] = __float_as_uint(Bh[kb + q + 4][c0]);
                bl[j][0] = __float_as_uint(Bl[kb + q][c0]);
                bl[j][1] = __float_as_uint(Bl[kb + q + 4][c0]);
            }
            #pragma unroll
            for (int i = 0; i < 4; i++)
                #pragma unroll
                for (int j = 0; j < 4; j++) {
                    mma_tf32(acc[i][j], ah[i], bh[j]);
                    mma_tf32(acc[i][j], ah[i], bl[j]);
                    mma_tf32(acc[i][j], al[i], bh[j]);
                }
        }
        __syncthreads();
    }

    // epilogue
    #pragma unroll
    for (int i = 0; i < 4; i++) {
        int r0 = rowBase + warpRow + i * 16 + g;
        #pragma unroll
        for (int j = 0; j < 4; j++) {
            int col = warpCol + j * 8 + 2 * q;
            float2 v0 = make_float2(acc[i][j][0], acc[i][j][1]);
            float2 v1 = make_float2(acc[i][j][2], acc[i][j][3]);
            if (!split) {
                if (r0 < nrows)     *(float2*)&Csel[(size_t)r0 * 128 + col] = v0;
                if (r0 + 8 < nrows) *(float2*)&Csel[(size_t)(r0 + 8) * 128 + col] = v1;
            } else {
                float* Cd; int cc;
                if (col < 64) { Cd = C0; cc = col; } else { Cd = C1; cc = col - 64; }
                if (r0 < nrows)     *(float2*)&Cd[(size_t)r0 * 64 + cc] = v0;
                if (r0 + 8 < nrows) *(float2*)&Cd[(size_t)(r0 + 8) * 64 + cc] = v1;
            }
        }
    }
}

// ---------------- aggregation layer 1: h = relu(sum y[src] + b1 + z) --------
__global__ __launch_bounds__(256) void k_agg1(const float* __restrict__ b1) {
    int node = blockIdx.x * (blockDim.x / 32) + (threadIdx.x >> 5);
    if (node >= NN) return;
    int lane = threadIdx.x & 31;
    int beg = g_rowptr[node], end = g_rowptr[node + 1];
    float4 bv = *(const float4*)&b1[lane * 4];
    float4 zv = *(const float4*)&g_z[(size_t)node * FH + lane * 4];
    float4 acc = make_float4(bv.x + zv.x, bv.y + zv.y, bv.z + zv.z, bv.w + zv.w);
    for (int p = beg; p < end; p++) {
        int s = g_col[p];
        float4 v = *(const float4*)&g_y[(size_t)s * FH + lane * 4];
        acc.x += v.x; acc.y += v.y; acc.z += v.z; acc.w += v.w;
    }
    acc.x = fmaxf(acc.x, 0.f); acc.y = fmaxf(acc.y, 0.f);
    acc.z = fmaxf(acc.z, 0.f); acc.w = fmaxf(acc.w, 0.f);
    *(float4*)&g_h[(size_t)node * FH + lane * 4] = acc;
}

// ---------------- aggregation layer 2: out = sum p[src] + b2 + q ------------
__global__ __launch_bounds__(256) void k_agg2(const float* __restrict__ b2,
                                              float* __restrict__ out) {
    int node = blockIdx.x * (blockDim.x / 32) + (threadIdx.x >> 5);
    if (node >= NN) return;
    int lane = threadIdx.x & 31;
    int beg = g_rowptr[node], end = g_rowptr[node + 1];
    float2 bv = *(const float2*)&b2[lane * 2];
    float2 qv = *(const float2*)&g_q[(size_t)node * FO + lane * 2];
    float2 acc = make_float2(bv.x + qv.x, bv.y + qv.y);
    for (int p = beg; p < end; p++) {
        int s = g_col[p];
        float2 v = *(const float2*)&g_p[(size_t)s * FO + lane * 2];
        acc.x += v.x; acc.y += v.y;
    }
    *(float2*)&out[(size_t)node * FO + lane * 2] = acc;
}

// ---------------- launch -----------------------------------------------------
extern "C" void kernel_launch(void* const* d_in, const int* in_sizes, int n_in,
                              void* d_out, int out_size) {
    (void)in_sizes; (void)n_in; (void)out_size;
    const float* x   = (const float*)d_in[0];
    const void*  ei  = d_in[1];
    const float* w1r = (const float*)d_in[2];
    const float* b1  = (const float*)d_in[3];
    const float* w1o = (const float*)d_in[4];
    const float* w2r = (const float*)d_in[5];
    const float* b2  = (const float*)d_in[6];
    const float* w2o = (const float*)d_in[7];
    float* out = (float*)d_out;

    float *yp, *zp, *hp, *pp, *qp;
    cudaGetSymbolAddress((void**)&yp, g_y);
    cudaGetSymbolAddress((void**)&zp, g_z);
    cudaGetSymbolAddress((void**)&hp, g_h);
    cudaGetSymbolAddress((void**)&pp, g_p);
    cudaGetSymbolAddress((void**)&qp, g_q);

    const int EB = (EE + 255) / 256;
    const int NB = (NN + 255) / 256;
    const int GB = (NN + 127) / 128;     // 782 gemm blocks
    const int AB = (NN + 7) / 8;         // agg blocks (8 warps/block)

    // CSR build
    k_detect<<<1, 256>>>((const int*)ei);
    k_zero_cnt<<<NB, 256>>>();
    k_count<<<EB, 256>>>(ei);
    k_scan1<<<NBLK_SCAN, 1024>>>();
    k_scan2<<<1, 128>>>();
    k_scan3<<<NBLK_SCAN, 1024>>>();
    k_fill<<<EB, 256>>>(ei);

    // layer 1: y = x@w1r, z = x@w1o (dual via gridDim.y)
    k_gemm_tf32<<<dim3(GB, 2), 256>>>(x, w1r, w1o, yp, zp, NN, 0);
    k_agg1<<<AB, 256>>>(b1);

    // layer 2: p = h@w2r, q = h@w2o (merged into one BN=128 GEMM)
    k_gemm_tf32<<<dim3(GB, 1), 256>>>(hp, w2r, w2o, pp, qp, NN, 1);
    k_agg2<<<AB, 256>>>(b2, out);
}

// round 4
// speedup vs baseline: 1.5450x; 1.2309x over previous
#include <cuda_runtime.h>
#include <cuda_bf16.h>

#define NN 100000
#define EE 1600000
#define F1 128
#define FH 128
#define FO 64
#define NBLK_SCAN ((NN + 1023) / 1024)   // 98

// ---------------- scratch (device globals; no allocations allowed) ----------
__device__ float g_y[(size_t)NN * FH];   // x @ w1_rel
__device__ float g_z[(size_t)NN * FH];   // x @ w1_root
__device__ float g_h[(size_t)NN * FH];   // hidden after relu
__device__ float g_p[(size_t)NN * FO];   // h @ w2_rel
__device__ float g_q[(size_t)NN * FO];   // h @ w2_root
__device__ int   g_rowptr[NN + 1];
__device__ int   g_cnt[NN];
__device__ int   g_cursor[NN];
__device__ int   g_col[EE];              // src node per CSR slot (dst-indexed)
__device__ int   g_is64;
__device__ int   g_bsum[NBLK_SCAN + 32];
__device__ int   g_bsumx[NBLK_SCAN + 32];

// ---------------- dtype detection: int64 vs int32 edge_index ----------------
__global__ void k_detect(const int* __restrict__ ebuf) {
    __shared__ int bad;
    if (threadIdx.x == 0) bad = 0;
    __syncthreads();
    for (int i = threadIdx.x; i < 2048; i += blockDim.x)
        if (ebuf[2 * i + 1] != 0) bad = 1;
    __syncthreads();
    if (threadIdx.x == 0) g_is64 = bad ? 0 : 1;
}

__global__ void k_zero_cnt() {
    int i = blockIdx.x * blockDim.x + threadIdx.x;
    if (i < NN) g_cnt[i] = 0;
}

__device__ __forceinline__ int edge_at(const void* ebuf, int is64, long long idx) {
    if (is64) return (int)((const long long*)ebuf)[idx];
    return ((const int*)ebuf)[idx];
}

__global__ void k_count(const void* __restrict__ ebuf) {
    int e = blockIdx.x * blockDim.x + threadIdx.x;
    if (e >= EE) return;
    int is64 = g_is64;
    int dst = edge_at(ebuf, is64, (long long)EE + e);
    atomicAdd(&g_cnt[dst], 1);
}

// ---------------- multi-block exclusive scan (3 phases) ---------------------
__global__ __launch_bounds__(1024) void k_scan1() {
    __shared__ int ws[32];
    int t = threadIdx.x;
    int idx = blockIdx.x * 1024 + t;
    int v = (idx < NN) ? g_cnt[idx] : 0;
    int x = v;
    #pragma unroll
    for (int o = 1; o < 32; o <<= 1) {
        int y = __shfl_up_sync(0xFFFFFFFFu, x, o);
        if ((t & 31) >= o) x += y;
    }
    if ((t & 31) == 31) ws[t >> 5] = x;
    __syncthreads();
    if (t < 32) {
        int w = ws[t];
        #pragma unroll
        for (int o = 1; o < 32; o <<= 1) {
            int y = __shfl_up_sync(0xFFFFFFFFu, w, o);
            if (t >= o) w += y;
        }
        ws[t] = w;
    }
    __syncthreads();
    int prefix = (t >= 32) ? ws[(t >> 5) - 1] : 0;
    int incl = x + prefix;
    if (idx < NN) g_rowptr[idx] = incl - v;
    if (t == 1023) g_bsum[blockIdx.x] = incl;
}

__global__ __launch_bounds__(128) void k_scan2() {
    int t = threadIdx.x;
    int v = (t < NBLK_SCAN) ? g_bsum[t] : 0;
    int x = v;
    #pragma unroll
    for (int o = 1; o < 32; o <<= 1) {
        int y = __shfl_up_sync(0xFFFFFFFFu, x, o);
        if ((t & 31) >= o) x += y;
    }
    __shared__ int ws[4];
    if ((t & 31) == 31) ws[t >> 5] = x;
    __syncthreads();
    if (t < 4) {
        int w = ws[t];
        #pragma unroll
        for (int o = 1; o < 4; o <<= 1) {
            int y = __shfl_up_sync(0xFu, w, o);
            if (t >= o) w += y;
        }
        ws[t] = w;
    }
    __syncthreads();
    int prefix = (t >= 32) ? ws[(t >> 5) - 1] : 0;
    if (t < NBLK_SCAN) g_bsumx[t] = x + prefix - v;
}

__global__ __launch_bounds__(1024) void k_scan3() {
    int t = threadIdx.x;
    int idx = blockIdx.x * 1024 + t;
    int off = g_bsumx[blockIdx.x];
    if (idx < NN) {
        int r = g_rowptr[idx] + off;
        g_rowptr[idx] = r;
        g_cursor[idx] = r;
    }
    if (idx == 0) g_rowptr[NN] = EE;
}

__global__ void k_fill(const void* __restrict__ ebuf) {
    int e = blockIdx.x * blockDim.x + threadIdx.x;
    if (e >= EE) return;
    int is64 = g_is64;
    int src = edge_at(ebuf, is64, e);
    int dst = edge_at(ebuf, is64, (long long)EE + e);
    int pos = atomicAdd(&g_cursor[dst], 1);
    g_col[pos] = src;
}

// ---------------- 3xBF16 tensor-core GEMM (fp32-class accuracy ~2e-5) -------
// Split each fp32 into hi=bf16(v), lo=bf16(v-hi); compute hi*hi + hi*lo + lo*hi.
// Smem holds {hiPair, loPair} interleaved as uint2 so one LDS.64 feeds both.
// Row-major [128][19] (19 = 16 + 3 pad, 19 mod 16 = 3) makes frag loads and
// conversion stores both exactly 2-phase on the smem crossbar.

__device__ __forceinline__ uint2 split2(float a, float b) {
    __nv_bfloat16 ha = __float2bfloat16(a), hb = __float2bfloat16(b);
    float ra = a - __bfloat162float(ha);
    float rb = b - __bfloat162float(hb);
    __nv_bfloat162 H = __halves2bfloat162(ha, hb);            // .x = a (lower k)
    __nv_bfloat162 L = __floats2bfloat162_rn(ra, rb);
    uint2 r;
    r.x = *reinterpret_cast<unsigned*>(&H);
    r.y = *reinterpret_cast<unsigned*>(&L);
    return r;
}

__device__ __forceinline__ void mma_bf16(float* c, const unsigned* a, const unsigned* b) {
    asm volatile(
        "mma.sync.aligned.m16n8k16.row.col.f32.bf16.bf16.f32 "
        "{%0,%1,%2,%3}, {%4,%5,%6,%7}, {%8,%9}, {%0,%1,%2,%3};\n"
        : "+f"(c[0]), "+f"(c[1]), "+f"(c[2]), "+f"(c[3])
        : "r"(a[0]), "r"(a[1]), "r"(a[2]), "r"(a[3]), "r"(b[0]), "r"(b[1]));
}

// C[nrows,128] = A[nrows,128] * B[128,128]
// split=0: B = W (128x128) chosen by blockIdx.y (two independent GEMMs).
// split=1: B = [W0 | W1] (each 128x64), outputs to C0 / C1.
__global__ __launch_bounds__(256, 2) void k_gemm_bf16(
    const float* __restrict__ A,
    const float* __restrict__ W0, const float* __restrict__ W1,
    float* __restrict__ C0, float* __restrict__ C1,
    int nrows, int split)
{
    __shared__ uint2 As[128][19];   // [row][kw-pair], pair = (k=2kw, 2kw+1)
    __shared__ uint2 Bs[128][19];   // [col][kw-pair]

    int tid = threadIdx.x;
    int wid = tid >> 5, lane = tid & 31;
    int g = lane >> 2, q = lane & 3;
    int warpRow = (wid >> 2) * 64;     // 2 warps over M
    int warpCol = (wid & 3) * 32;      // 4 warps over N
    int rowBase = blockIdx.x * 128;

    const float* Wsel = (blockIdx.y == 0) ? W0 : W1;
    float* Csel = (blockIdx.y == 0) ? C0 : C1;

    float acc[4][4][4];
    #pragma unroll
    for (int i = 0; i < 4; i++)
        #pragma unroll
        for (int j = 0; j < 4; j++)
            #pragma unroll
            for (int r = 0; r < 4; r++) acc[i][j][r] = 0.f;

    for (int k0 = 0; k0 < 128; k0 += 32) {
        // A tile: 128 rows x 32 k = 2048 float2 tasks, 8 per thread.
        // Within a warp: kw fastest (coalesced global), 2 rows -> 2-phase STS.
        #pragma unroll
        for (int it = 0; it < 8; it++) {
            int s = it * 256 + tid;
            int kw = s & 15;
            int row = s >> 4;
            float2 v = make_float2(0.f, 0.f);
            int gr = rowBase + row;
            if (gr < nrows) v = *(const float2*)&A[(size_t)gr * 128 + k0 + 2 * kw];
            As[row][kw] = split2(v.x, v.y);
        }
        // B tile: 32 k x 128 cols = 2048 pair tasks (pair along k), 8 per thread.
        // Within a warp: col fastest (coalesced global), kw const -> 2-phase STS.
        #pragma unroll
        for (int it = 0; it < 8; it++) {
            int s = it * 256 + tid;
            int col = s & 127;
            int kw = s >> 7;
            int kg = k0 + 2 * kw;
            float v0, v1;
            if (!split) {
                v0 = Wsel[(size_t)kg * 128 + col];
                v1 = Wsel[(size_t)(kg + 1) * 128 + col];
            } else {
                const float* Wp = (col < 64) ? W0 : W1;
                int cw = col & 63;
                v0 = Wp[(size_t)kg * 64 + cw];
                v1 = Wp[(size_t)(kg + 1) * 64 + cw];
            }
            Bs[col][kw] = split2(v0, v1);
        }
        __syncthreads();

        #pragma unroll
        for (int t = 0; t < 2; t++) {
            int p0 = t * 8 + q, p1 = p0 + 4;
            uint2 bfr[4][2];
            #pragma unroll
            for (int j = 0; j < 4; j++) {
                int col = warpCol + j * 8 + g;
                bfr[j][0] = Bs[col][p0];
                bfr[j][1] = Bs[col][p1];
            }
            #pragma unroll
            for (int i = 0; i < 4; i++) {
                int r0 = warpRow + i * 16 + g;
                uint2 a0 = As[r0][p0],     a1 = As[r0 + 8][p0];
                uint2 a2 = As[r0][p1],     a3 = As[r0 + 8][p1];
                unsigned ah[4] = {a0.x, a1.x, a2.x, a3.x};
                unsigned al[4] = {a0.y, a1.y, a2.y, a3.y};
                #pragma unroll
                for (int j = 0; j < 4; j++) {
                    unsigned bh[2] = {bfr[j][0].x, bfr[j][1].x};
                    unsigned bl[2] = {bfr[j][0].y, bfr[j][1].y};
                    mma_bf16(acc[i][j], ah, bh);
                    mma_bf16(acc[i][j], ah, bl);
                    mma_bf16(acc[i][j], al, bh);
                }
            }
        }
        __syncthreads();
    }

    // epilogue
    #pragma unroll
    for (int i = 0; i < 4; i++) {
        int r0 = rowBase + warpRow + i * 16 + g;
        #pragma unroll
        for (int j = 0; j < 4; j++) {
            int col = warpCol + j * 8 + 2 * q;
            float2 v0 = make_float2(acc[i][j][0], acc[i][j][1]);
            float2 v1 = make_float2(acc[i][j][2], acc[i][j][3]);
            if (!split) {
                if (r0 < nrows)     *(float2*)&Csel[(size_t)r0 * 128 + col] = v0;
                if (r0 + 8 < nrows) *(float2*)&Csel[(size_t)(r0 + 8) * 128 + col] = v1;
            } else {
                float* Cd; int cc;
                if (col < 64) { Cd = C0; cc = col; } else { Cd = C1; cc = col - 64; }
                if (r0 < nrows)     *(float2*)&Cd[(size_t)r0 * 64 + cc] = v0;
                if (r0 + 8 < nrows) *(float2*)&Cd[(size_t)(r0 + 8) * 64 + cc] = v1;
            }
        }
    }
}

// ---------------- aggregation layer 1: h = relu(sum y[src] + b1 + z) --------
__global__ __launch_bounds__(256) void k_agg1(const float* __restrict__ b1) {
    int node = blockIdx.x * (blockDim.x / 32) + (threadIdx.x >> 5);
    if (node >= NN) return;
    int lane = threadIdx.x & 31;
    int beg = g_rowptr[node], end = g_rowptr[node + 1];
    float4 bv = *(const float4*)&b1[lane * 4];
    float4 zv = *(const float4*)&g_z[(size_t)node * FH + lane * 4];
    float4 acc = make_float4(bv.x + zv.x, bv.y + zv.y, bv.z + zv.z, bv.w + zv.w);
    for (int p = beg; p < end; p++) {
        int s = g_col[p];
        float4 v = *(const float4*)&g_y[(size_t)s * FH + lane * 4];
        acc.x += v.x; acc.y += v.y; acc.z += v.z; acc.w += v.w;
    }
    acc.x = fmaxf(acc.x, 0.f); acc.y = fmaxf(acc.y, 0.f);
    acc.z = fmaxf(acc.z, 0.f); acc.w = fmaxf(acc.w, 0.f);
    *(float4*)&g_h[(size_t)node * FH + lane * 4] = acc;
}

// ---------------- aggregation layer 2: out = sum p[src] + b2 + q ------------
__global__ __launch_bounds__(256) void k_agg2(const float* __restrict__ b2,
                                              float* __restrict__ out) {
    int node = blockIdx.x * (blockDim.x / 32) + (threadIdx.x >> 5);
    if (node >= NN) return;
    int lane = threadIdx.x & 31;
    int beg = g_rowptr[node], end = g_rowptr[node + 1];
    float2 bv = *(const float2*)&b2[lane * 2];
    float2 qv = *(const float2*)&g_q[(size_t)node * FO + lane * 2];
    float2 acc = make_float2(bv.x + qv.x, bv.y + qv.y);
    for (int p = beg; p < end; p++) {
        int s = g_col[p];
        float2 v = *(const float2*)&g_p[(size_t)s * FO + lane * 2];
        acc.x += v.x; acc.y += v.y;
    }
    *(float2*)&out[(size_t)node * FO + lane * 2] = acc;
}

// ---------------- launch -----------------------------------------------------
extern "C" void kernel_launch(void* const* d_in, const int* in_sizes, int n_in,
                              void* d_out, int out_size) {
    (void)in_sizes; (void)n_in; (void)out_size;
    const float* x   = (const float*)d_in[0];
    const void*  ei  = d_in[1];
    const float* w1r = (const float*)d_in[2];
    const float* b1  = (const float*)d_in[3];
    const float* w1o = (const float*)d_in[4];
    const float* w2r = (const float*)d_in[5];
    const float* b2  = (const float*)d_in[6];
    const float* w2o = (const float*)d_in[7];
    float* out = (float*)d_out;

    float *yp, *zp, *hp, *pp, *qp;
    cudaGetSymbolAddress((void**)&yp, g_y);
    cudaGetSymbolAddress((void**)&zp, g_z);
    cudaGetSymbolAddress((void**)&hp, g_h);
    cudaGetSymbolAddress((void**)&pp, g_p);
    cudaGetSymbolAddress((void**)&qp, g_q);

    const int EB = (EE + 255) / 256;
    const int NB = (NN + 255) / 256;
    const int GB = (NN + 127) / 128;     // 782 gemm blocks
    const int AB = (NN + 7) / 8;         // agg blocks (8 warps/block)

    // CSR build
    k_detect<<<1, 256>>>((const int*)ei);
    k_zero_cnt<<<NB, 256>>>();
    k_count<<<EB, 256>>>(ei);
    k_scan1<<<NBLK_SCAN, 1024>>>();
    k_scan2<<<1, 128>>>();
    k_scan3<<<NBLK_SCAN, 1024>>>();
    k_fill<<<EB, 256>>>(ei);

    // layer 1: y = x@w1r, z = x@w1o (dual via gridDim.y)
    k_gemm_bf16<<<dim3(GB, 2), 256>>>(x, w1r, w1o, yp, zp, NN, 0);
    k_agg1<<<AB, 256>>>(b1);

    // layer 2: p = h@w2r, q = h@w2o (merged into one BN=128 GEMM)
    k_gemm_bf16<<<dim3(GB, 1), 256>>>(hp, w2r, w2o, pp, qp, NN, 1);
    k_agg2<<<AB, 256>>>(b2, out);
}

// round 5
// speedup vs baseline: 1.5646x; 1.0127x over previous
#include <cuda_runtime.h>
#include <cuda_bf16.h>

#define NN 100000
#define EE 1600000
#define FH 128
#define FO 64
#define NBLK_SCAN ((NN + 1023) / 1024)   // 98

// ---------------- scratch (device globals; no allocations allowed) ----------
__device__ float g_y[(size_t)NN * FH];            // x @ w1_rel
__device__ float g_z[(size_t)NN * FH];            // x @ w1_root
__device__ float g_p[(size_t)NN * FO];            // h @ w2_rel
__device__ float g_q[(size_t)NN * FO];            // h @ w2_root
__device__ __align__(16) uint2 g_xs[(size_t)NN * 64];   // x pre-split (hi,lo bf16x2 pairs)
__device__ __align__(16) uint2 g_hs[(size_t)NN * 64];   // h pre-split
__device__ __align__(16) uint2 g_w1s[2 * 128 * 64];     // [sel][col][kw] w1_rel / w1_root
__device__ __align__(16) uint2 g_w2s[128 * 64];         // [col][kw] (cols 0-63 w2r, 64-127 w2o)
__device__ int   g_rowptr[NN + 1];
__device__ int   g_cnt[NN];
__device__ int   g_cursor[NN];
__device__ int   g_col[EE];
__device__ int   g_is64;
__device__ int   g_bsum[NBLK_SCAN + 32];
__device__ int   g_bsumx[NBLK_SCAN + 32];

// ---------------- split helpers ---------------------------------------------
__device__ __forceinline__ uint2 split2(float a, float b) {
    __nv_bfloat16 ha = __float2bfloat16(a), hb = __float2bfloat16(b);
    float ra = a - __bfloat162float(ha);
    float rb = b - __bfloat162float(hb);
    __nv_bfloat162 H = __halves2bfloat162(ha, hb);            // .x = lower k
    __nv_bfloat162 L = __floats2bfloat162_rn(ra, rb);
    uint2 r;
    r.x = *reinterpret_cast<unsigned*>(&H);
    r.y = *reinterpret_cast<unsigned*>(&L);
    return r;
}

// ---------------- dtype detection: int64 vs int32 edge_index ----------------
__global__ void k_detect(const int* __restrict__ ebuf) {
    __shared__ int bad;
    if (threadIdx.x == 0) bad = 0;
    __syncthreads();
    for (int i = threadIdx.x; i < 2048; i += blockDim.x)
        if (ebuf[2 * i + 1] != 0) bad = 1;
    __syncthreads();
    if (threadIdx.x == 0) g_is64 = bad ? 0 : 1;
}

__global__ void k_zero_cnt() {
    int i = blockIdx.x * blockDim.x + threadIdx.x;
    if (i < NN) g_cnt[i] = 0;
}

__device__ __forceinline__ int edge_at(const void* ebuf, int is64, long long idx) {
    if (is64) return (int)((const long long*)ebuf)[idx];
    return ((const int*)ebuf)[idx];
}

__global__ void k_count(const void* __restrict__ ebuf) {
    int e = blockIdx.x * blockDim.x + threadIdx.x;
    if (e >= EE) return;
    int is64 = g_is64;
    int dst = edge_at(ebuf, is64, (long long)EE + e);
    atomicAdd(&g_cnt[dst], 1);
}

// ---------------- multi-block exclusive scan (3 phases) ---------------------
__global__ __launch_bounds__(1024) void k_scan1() {
    __shared__ int ws[32];
    int t = threadIdx.x;
    int idx = blockIdx.x * 1024 + t;
    int v = (idx < NN) ? g_cnt[idx] : 0;
    int x = v;
    #pragma unroll
    for (int o = 1; o < 32; o <<= 1) {
        int y = __shfl_up_sync(0xFFFFFFFFu, x, o);
        if ((t & 31) >= o) x += y;
    }
    if ((t & 31) == 31) ws[t >> 5] = x;
    __syncthreads();
    if (t < 32) {
        int w = ws[t];
        #pragma unroll
        for (int o = 1; o < 32; o <<= 1) {
            int y = __shfl_up_sync(0xFFFFFFFFu, w, o);
            if (t >= o) w += y;
        }
        ws[t] = w;
    }
    __syncthreads();
    int prefix = (t >= 32) ? ws[(t >> 5) - 1] : 0;
    int incl = x + prefix;
    if (idx < NN) g_rowptr[idx] = incl - v;
    if (t == 1023) g_bsum[blockIdx.x] = incl;
}

__global__ __launch_bounds__(128) void k_scan2() {
    int t = threadIdx.x;
    int v = (t < NBLK_SCAN) ? g_bsum[t] : 0;
    int x = v;
    #pragma unroll
    for (int o = 1; o < 32; o <<= 1) {
        int y = __shfl_up_sync(0xFFFFFFFFu, x, o);
        if ((t & 31) >= o) x += y;
    }
    __shared__ int ws[4];
    if ((t & 31) == 31) ws[t >> 5] = x;
    __syncthreads();
    if (t < 4) {
        int w = ws[t];
        #pragma unroll
        for (int o = 1; o < 4; o <<= 1) {
            int y = __shfl_up_sync(0xFu, w, o);
            if (t >= o) w += y;
        }
        ws[t] = w;
    }
    __syncthreads();
    int prefix = (t >= 32) ? ws[(t >> 5) - 1] : 0;
    if (t < NBLK_SCAN) g_bsumx[t] = x + prefix - v;
}

__global__ __launch_bounds__(1024) void k_scan3() {
    int t = threadIdx.x;
    int idx = blockIdx.x * 1024 + t;
    int off = g_bsumx[blockIdx.x];
    if (idx < NN) {
        int r = g_rowptr[idx] + off;
        g_rowptr[idx] = r;
        g_cursor[idx] = r;
    }
    if (idx == 0) g_rowptr[NN] = EE;
}

__global__ void k_fill(const void* __restrict__ ebuf) {
    int e = blockIdx.x * blockDim.x + threadIdx.x;
    if (e >= EE) return;
    int is64 = g_is64;
    int src = edge_at(ebuf, is64, e);
    int dst = edge_at(ebuf, is64, (long long)EE + e);
    int pos = atomicAdd(&g_cursor[dst], 1);
    g_col[pos] = src;
}

// ---------------- pre-split kernels ------------------------------------------
// x: [NN][128] fp32 -> g_xs [NN][64] pairs. 2 pairs (float4) per thread.
__global__ __launch_bounds__(256) void k_split_x(const float* __restrict__ x) {
    int idx = blockIdx.x * blockDim.x + threadIdx.x;   // uint4 task
    if (idx >= NN * 32) return;
    int row = idx >> 5, q4 = idx & 31;
    float4 v = *(const float4*)&x[(size_t)row * 128 + q4 * 4];
    uint2 s0 = split2(v.x, v.y);
    uint2 s1 = split2(v.z, v.w);
    uint4 pk = make_uint4(s0.x, s0.y, s1.x, s1.y);
    *(uint4*)&g_xs[(size_t)row * 64 + q4 * 2] = pk;
}

// w1: two 128x128 -> g_w1s[sel][col][kw] = split2(W[2kw][col], W[2kw+1][col])
__global__ __launch_bounds__(256) void k_split_w1(const float* __restrict__ w1r,
                                                  const float* __restrict__ w1o) {
    int idx = blockIdx.x * blockDim.x + threadIdx.x;
    if (idx >= 2 * 128 * 64) return;
    int sel = idx >> 13;
    int rem = idx & 8191;
    int col = rem >> 6, kw = rem & 63;
    const float* W = sel ? w1o : w1r;
    float v0 = W[(size_t)(2 * kw) * 128 + col];
    float v1 = W[(size_t)(2 * kw + 1) * 128 + col];
    g_w1s[idx] = split2(v0, v1);
}

// w2: two 128x64 -> combined g_w2s[col][kw]; cols 0-63 from w2r, 64-127 from w2o
__global__ __launch_bounds__(256) void k_split_w2(const float* __restrict__ w2r,
                                                  const float* __restrict__ w2o) {
    int idx = blockIdx.x * blockDim.x + threadIdx.x;
    if (idx >= 128 * 64) return;
    int col = idx >> 6, kw = idx & 63;
    const float* W = (col < 64) ? w2r : w2o;
    int c = col & 63;
    float v0 = W[(size_t)(2 * kw) * 64 + c];
    float v1 = W[(size_t)(2 * kw + 1) * 64 + c];
    g_w2s[idx] = split2(v0, v1);
}

// ---------------- 3xBF16 tensor-core GEMM on pre-split operands -------------
__device__ __forceinline__ void mma_bf16(float* c, const unsigned* a, const unsigned* b) {
    asm volatile(
        "mma.sync.aligned.m16n8k16.row.col.f32.bf16.bf16.f32 "
        "{%0,%1,%2,%3}, {%4,%5,%6,%7}, {%8,%9}, {%0,%1,%2,%3};\n"
        : "+f"(c[0]), "+f"(c[1]), "+f"(c[2]), "+f"(c[3])
        : "r"(a[0]), "r"(a[1]), "r"(a[2]), "r"(a[3]), "r"(b[0]), "r"(b[1]));
}

// C[nrows,128] = A[nrows,128] * B  (A, B pre-split pairs)
// split=0: B = B0/B1 chosen by blockIdx.y (two independent GEMMs, 128-wide C).
// split=1: B = B0 combined (cols 0-63 -> C0, 64-127 -> C1, each 64-wide).
__global__ __launch_bounds__(256, 2) void k_gemm_pre(
    const uint2* __restrict__ A,
    const uint2* __restrict__ B0, const uint2* __restrict__ B1,
    float* __restrict__ C0, float* __restrict__ C1,
    int nrows, int split)
{
    __shared__ __align__(16) uint2 As[128][20];   // [row][kw], pad 20 for 16B STS + 2-phase LDS
    __shared__ __align__(16) uint2 Bs[128][20];   // [col][kw]

    int tid = threadIdx.x;
    int wid = tid >> 5, lane = tid & 31;
    int g = lane >> 2, q = lane & 3;
    int warpRow = (wid >> 2) * 64;     // 2 warps over M
    int warpCol = (wid & 3) * 32;      // 4 warps over N
    int rowBase = blockIdx.x * 128;

    const uint2* Bsel = (!split) ? ((blockIdx.y == 0) ? B0 : B1) : B0;
    float* Csel = (blockIdx.y == 0) ? C0 : C1;

    float acc[4][4][4];
    #pragma unroll
    for (int i = 0; i < 4; i++)
        #pragma unroll
        for (int j = 0; j < 4; j++)
            #pragma unroll
            for (int r = 0; r < 4; r++) acc[i][j][r] = 0.f;

    for (int k0w = 0; k0w < 64; k0w += 16) {
        // A tile: 128 rows x 16 kw, uint4 (2 pairs) granularity: 1024 tasks, 4/thread
        #pragma unroll
        for (int it = 0; it < 4; it++) {
            int s = it * 256 + tid;
            int kw2 = s & 7;
            int row = s >> 3;
            uint4 v = make_uint4(0u, 0u, 0u, 0u);
            int gr = rowBase + row;
            if (gr < nrows) v = *(const uint4*)&A[(size_t)gr * 64 + k0w + kw2 * 2];
            *(uint4*)&As[row][kw2 * 2] = v;
        }
        // B tile: 128 cols x 16 kw
        #pragma unroll
        for (int it = 0; it < 4; it++) {
            int s = it * 256 + tid;
            int kw2 = s & 7;
            int col = s >> 3;
            *(uint4*)&Bs[col][kw2 * 2] = *(const uint4*)&Bsel[(size_t)col * 64 + k0w + kw2 * 2];
        }
        __syncthreads();

        #pragma unroll
        for (int t = 0; t < 2; t++) {
            int p0 = t * 8 + q, p1 = p0 + 4;
            uint2 bfr[4][2];
            #pragma unroll
            for (int j = 0; j < 4; j++) {
                int col = warpCol + j * 8 + g;
                bfr[j][0] = Bs[col][p0];
                bfr[j][1] = Bs[col][p1];
            }
            #pragma unroll
            for (int i = 0; i < 4; i++) {
                int r0 = warpRow + i * 16 + g;
                uint2 a0 = As[r0][p0], a1 = As[r0 + 8][p0];
                uint2 a2 = As[r0][p1], a3 = As[r0 + 8][p1];
                unsigned ah[4] = {a0.x, a1.x, a2.x, a3.x};
                unsigned al[4] = {a0.y, a1.y, a2.y, a3.y};
                #pragma unroll
                for (int j = 0; j < 4; j++) {
                    unsigned bh[2] = {bfr[j][0].x, bfr[j][1].x};
                    unsigned bl[2] = {bfr[j][0].y, bfr[j][1].y};
                    mma_bf16(acc[i][j], ah, bh);
                    mma_bf16(acc[i][j], ah, bl);
                    mma_bf16(acc[i][j], al, bh);
                }
            }
        }
        __syncthreads();
    }

    // epilogue
    #pragma unroll
    for (int i = 0; i < 4; i++) {
        int r0 = rowBase + warpRow + i * 16 + g;
        #pragma unroll
        for (int j = 0; j < 4; j++) {
            int col = warpCol + j * 8 + 2 * q;
            float2 v0 = make_float2(acc[i][j][0], acc[i][j][1]);
            float2 v1 = make_float2(acc[i][j][2], acc[i][j][3]);
            if (!split) {
                if (r0 < nrows)     *(float2*)&Csel[(size_t)r0 * 128 + col] = v0;
                if (r0 + 8 < nrows) *(float2*)&Csel[(size_t)(r0 + 8) * 128 + col] = v1;
            } else {
                float* Cd; int cc;
                if (col < 64) { Cd = C0; cc = col; } else { Cd = C1; cc = col - 64; }
                if (r0 < nrows)     *(float2*)&Cd[(size_t)r0 * 64 + cc] = v0;
                if (r0 + 8 < nrows) *(float2*)&Cd[(size_t)(r0 + 8) * 64 + cc] = v1;
            }
        }
    }
}

// ---------------- aggregation layer 1: h = relu(sum y[src] + b1 + z) --------
// Writes h directly in pre-split pair form (free split for layer-2 GEMM).
__global__ __launch_bounds__(256) void k_agg1(const float* __restrict__ b1) {
    int node = blockIdx.x * (blockDim.x / 32) + (threadIdx.x >> 5);
    if (node >= NN) return;
    int lane = threadIdx.x & 31;
    int beg = g_rowptr[node], end = g_rowptr[node + 1];
    float4 bv = *(const float4*)&b1[lane * 4];
    float4 zv = *(const float4*)&g_z[(size_t)node * FH + lane * 4];
    float4 acc = make_float4(bv.x + zv.x, bv.y + zv.y, bv.z + zv.z, bv.w + zv.w);
    for (int p = beg; p < end; p++) {
        int s = g_col[p];
        float4 v = *(const float4*)&g_y[(size_t)s * FH + lane * 4];
        acc.x += v.x; acc.y += v.y; acc.z += v.z; acc.w += v.w;
    }
    acc.x = fmaxf(acc.x, 0.f); acc.y = fmaxf(acc.y, 0.f);
    acc.z = fmaxf(acc.z, 0.f); acc.w = fmaxf(acc.w, 0.f);
    uint2 s0 = split2(acc.x, acc.y);
    uint2 s1 = split2(acc.z, acc.w);
    *(uint4*)&g_hs[(size_t)node * 64 + lane * 2] = make_uint4(s0.x, s0.y, s1.x, s1.y);
}

// ---------------- aggregation layer 2: out = sum p[src] + b2 + q ------------
__global__ __launch_bounds__(256) void k_agg2(const float* __restrict__ b2,
                                              float* __restrict__ out) {
    int node = blockIdx.x * (blockDim.x / 32) + (threadIdx.x >> 5);
    if (node >= NN) return;
    int lane = threadIdx.x & 31;
    int beg = g_rowptr[node], end = g_rowptr[node + 1];
    float2 bv = *(const float2*)&b2[lane * 2];
    float2 qv = *(const float2*)&g_q[(size_t)node * FO + lane * 2];
    float2 acc = make_float2(bv.x + qv.x, bv.y + qv.y);
    for (int p = beg; p < end; p++) {
        int s = g_col[p];
        float2 v = *(const float2*)&g_p[(size_t)s * FO + lane * 2];
        acc.x += v.x; acc.y += v.y;
    }
    *(float2*)&out[(size_t)node * FO + lane * 2] = acc;
}

// ---------------- launch -----------------------------------------------------
extern "C" void kernel_launch(void* const* d_in, const int* in_sizes, int n_in,
                              void* d_out, int out_size) {
    (void)in_sizes; (void)n_in; (void)out_size;
    const float* x   = (const float*)d_in[0];
    const void*  ei  = d_in[1];
    const float* w1r = (const float*)d_in[2];
    const float* b1  = (const float*)d_in[3];
    const float* w1o = (const float*)d_in[4];
    const float* w2r = (const float*)d_in[5];
    const float* b2  = (const float*)d_in[6];
    const float* w2o = (const float*)d_in[7];
    float* out = (float*)d_out;

    float *yp, *zp, *pp, *qp;
    uint2 *xsp, *hsp, *w1sp, *w2sp;
    cudaGetSymbolAddress((void**)&yp, g_y);
    cudaGetSymbolAddress((void**)&zp, g_z);
    cudaGetSymbolAddress((void**)&pp, g_p);
    cudaGetSymbolAddress((void**)&qp, g_q);
    cudaGetSymbolAddress((void**)&xsp, g_xs);
    cudaGetSymbolAddress((void**)&hsp, g_hs);
    cudaGetSymbolAddress((void**)&w1sp, g_w1s);
    cudaGetSymbolAddress((void**)&w2sp, g_w2s);

    const int EB = (EE + 255) / 256;
    const int NB = (NN + 255) / 256;
    const int GB = (NN + 127) / 128;     // 782 gemm blocks
    const int AB = (NN + 7) / 8;         // agg blocks (8 warps/block)
    const int XB = (NN * 32 + 255) / 256;

    // pre-splits
    k_split_x<<<XB, 256>>>(x);
    k_split_w1<<<(2 * 128 * 64 + 255) / 256, 256>>>(w1r, w1o);
    k_split_w2<<<(128 * 64 + 255) / 256, 256>>>(w2r, w2o);

    // CSR build
    k_detect<<<1, 256>>>((const int*)ei);
    k_zero_cnt<<<NB, 256>>>();
    k_count<<<EB, 256>>>(ei);
    k_scan1<<<NBLK_SCAN, 1024>>>();
    k_scan2<<<1, 128>>>();
    k_scan3<<<NBLK_SCAN, 1024>>>();
    k_fill<<<EB, 256>>>(ei);

    // layer 1: y = x@w1r, z = x@w1o (dual via gridDim.y)
    k_gemm_pre<<<dim3(GB, 2), 256>>>(xsp, w1sp, w1sp + 128 * 64, yp, zp, NN, 0);
    k_agg1<<<AB, 256>>>(b1);

    // layer 2: p = h@w2r, q = h@w2o (merged, pre-split h)
    k_gemm_pre<<<dim3(GB, 1), 256>>>(hsp, w2sp, w2sp, pp, qp, NN, 1);
    k_agg2<<<AB, 256>>>(b2, out);
}

// round 7
// speedup vs baseline: 1.6618x; 1.0622x over previous
#include <cuda_runtime.h>
#include <cuda_bf16.h>
#include <cstdint>

#define NN 100000
#define EE 1600000
#define TILES 782                        // ceil(NN/128)
#define NROWS_PAD ((size_t)TILES * 128)  // 100096
#define NBLK_SCAN ((NN + 1023) / 1024)   // 98

// ---------------- scratch (device globals; no allocations allowed) ----------
// Pre-split pair images padded to full tiles; tail rows stay zero-initialized.
__device__ __align__(16) uint2 g_xs[NROWS_PAD * 64];
__device__ __align__(16) uint2 g_hs[NROWS_PAD * 64];
__device__ __align__(16) uint2 g_w1s[2 * 128 * 64];
__device__ __align__(16) uint2 g_w2s[128 * 64];
__device__ float g_y[(size_t)NN * 128];
__device__ float g_z[(size_t)NN * 128];
__device__ float g_p[(size_t)NN * 64];
__device__ float g_q[(size_t)NN * 64];
__device__ int   g_rowptr[NN + 1];
__device__ int   g_cnt[NN];
__device__ int   g_cursor[NN];
__device__ int   g_col[EE];
__device__ int   g_is64;
__device__ int   g_bsum[NBLK_SCAN + 32];
__device__ int   g_bsumx[NBLK_SCAN + 32];

// ---------------- helpers ----------------------------------------------------
__device__ __forceinline__ uint2 split2(float a, float b) {
    __nv_bfloat16 ha = __float2bfloat16(a), hb = __float2bfloat16(b);
    float ra = a - __bfloat162float(ha);
    float rb = b - __bfloat162float(hb);
    __nv_bfloat162 H = __halves2bfloat162(ha, hb);
    __nv_bfloat162 L = __floats2bfloat162_rn(ra, rb);
    uint2 r;
    r.x = *reinterpret_cast<unsigned*>(&H);
    r.y = *reinterpret_cast<unsigned*>(&L);
    return r;
}

__device__ __forceinline__ void mma_bf16(float* c, const unsigned* a, const unsigned* b) {
    asm volatile(
        "mma.sync.aligned.m16n8k16.row.col.f32.bf16.bf16.f32 "
        "{%0,%1,%2,%3}, {%4,%5,%6,%7}, {%8,%9}, {%0,%1,%2,%3};\n"
        : "+f"(c[0]), "+f"(c[1]), "+f"(c[2]), "+f"(c[3])
        : "r"(a[0]), "r"(a[1]), "r"(a[2]), "r"(a[3]), "r"(b[0]), "r"(b[1]));
}

__device__ __forceinline__ void cp16(uint32_t dst, const void* src) {
    asm volatile("cp.async.cg.shared.global [%0], [%1], 16;\n"
                 :: "r"(dst), "l"(__cvta_generic_to_global(src)) : "memory");
}

// ---------------- pre-split kernels ------------------------------------------
__global__ __launch_bounds__(256) void k_split_x(const float* __restrict__ x) {
    int idx = blockIdx.x * blockDim.x + threadIdx.x;
    if (idx >= NN * 32) return;
    int row = idx >> 5, q4 = idx & 31;
    float4 v = *(const float4*)&x[(size_t)row * 128 + q4 * 4];
    uint2 s0 = split2(v.x, v.y);
    uint2 s1 = split2(v.z, v.w);
    *(uint4*)&g_xs[(size_t)row * 64 + q4 * 2] = make_uint4(s0.x, s0.y, s1.x, s1.y);
}

__global__ __launch_bounds__(256) void k_split_w1(const float* __restrict__ w1r,
                                                  const float* __restrict__ w1o) {
    int idx = blockIdx.x * blockDim.x + threadIdx.x;
    if (idx >= 2 * 128 * 64) return;
    int sel = idx >> 13;
    int rem = idx & 8191;
    int col = rem >> 6, kw = rem & 63;
    const float* W = sel ? w1o : w1r;
    g_w1s[idx] = split2(W[(size_t)(2 * kw) * 128 + col],
                        W[(size_t)(2 * kw + 1) * 128 + col]);
}

__global__ __launch_bounds__(256) void k_split_w2(const float* __restrict__ w2r,
                                                  const float* __restrict__ w2o) {
    int idx = blockIdx.x * blockDim.x + threadIdx.x;
    if (idx >= 128 * 64) return;
    int col = idx >> 6, kw = idx & 63;
    const float* W = (col < 64) ? w2r : w2o;
    int c = col & 63;
    g_w2s[idx] = split2(W[(size_t)(2 * kw) * 64 + c],
                        W[(size_t)(2 * kw + 1) * 64 + c]);
}

// ---------------- 3xBF16 mma.sync GEMM, cp.async double-buffered -------------
// smem (dynamic, uint2 units): As[stage][128][20] at stage*2560,
//                              Bs[stage][128][20] at 5120 + stage*2560.
__global__ __launch_bounds__(256, 2) void k_gemm_pre(
    const uint2* __restrict__ A,
    const uint2* __restrict__ B0, const uint2* __restrict__ B1,
    float* __restrict__ C0, float* __restrict__ C1,
    int split)
{
    extern __shared__ __align__(16) uint2 sm[];
    uint32_t sbase = (uint32_t)__cvta_generic_to_shared(sm);

    int tid = threadIdx.x;
    int wid = tid >> 5, lane = tid & 31;
    int g = lane >> 2, q = lane & 3;
    int warpRow = (wid >> 2) * 64;
    int warpCol = (wid & 3) * 32;
    size_t rowBase = (size_t)blockIdx.x * 128;

    const uint2* Bsel = (!split) ? ((blockIdx.y == 0) ? B0 : B1) : B0;
    float* Csel = (blockIdx.y == 0) ? C0 : C1;

    float acc[4][4][4];
    #pragma unroll
    for (int i = 0; i < 4; i++)
        #pragma unroll
        for (int j = 0; j < 4; j++)
            #pragma unroll
            for (int r = 0; r < 4; r++) acc[i][j][r] = 0.f;

    // copy one 16-kw chunk (A 1024 uint4 + B 1024 uint4) into stage
    auto copy_chunk = [&](int c, int stage) {
        int k0w = c * 16;
        #pragma unroll
        for (int it = 0; it < 4; it++) {
            int s = it * 256 + tid;
            int kw2 = s & 7;
            int row = s >> 3;
            uint32_t dst = sbase + (uint32_t)((stage * 2560 + row * 20 + kw2 * 2) * 8);
            cp16(dst, &A[(rowBase + row) * 64 + k0w + kw2 * 2]);
        }
        #pragma unroll
        for (int it = 0; it < 4; it++) {
            int s = it * 256 + tid;
            int kw2 = s & 7;
            int col = s >> 3;
            uint32_t dst = sbase + (uint32_t)((5120 + stage * 2560 + col * 20 + kw2 * 2) * 8);
            cp16(dst, &Bsel[(size_t)col * 64 + k0w + kw2 * 2]);
        }
        asm volatile("cp.async.commit_group;\n" ::: "memory");
    };

    copy_chunk(0, 0);

    for (int c = 0; c < 4; c++) {
        int stage = c & 1;
        if (c + 1 < 4) {
            copy_chunk(c + 1, (c + 1) & 1);
            asm volatile("cp.async.wait_group 1;\n" ::: "memory");
        } else {
            asm volatile("cp.async.wait_group 0;\n" ::: "memory");
        }
        __syncthreads();

        uint2 (*As)[20] = (uint2(*)[20])(sm + stage * 2560);
        uint2 (*Bs)[20] = (uint2(*)[20])(sm + 5120 + stage * 2560);

        #pragma unroll
        for (int t = 0; t < 2; t++) {
            int p0 = t * 8 + q, p1 = p0 + 4;
            uint2 bfr[4][2];
            #pragma unroll
            for (int j = 0; j < 4; j++) {
                int col = warpCol + j * 8 + g;
                bfr[j][0] = Bs[col][p0];
                bfr[j][1] = Bs[col][p1];
            }
            #pragma unroll
            for (int i = 0; i < 4; i++) {
                int r0 = warpRow + i * 16 + g;
                uint2 a0 = As[r0][p0], a1 = As[r0 + 8][p0];
                uint2 a2 = As[r0][p1], a3 = As[r0 + 8][p1];
                unsigned ah[4] = {a0.x, a1.x, a2.x, a3.x};
                unsigned al[4] = {a0.y, a1.y, a2.y, a3.y};
                #pragma unroll
                for (int j = 0; j < 4; j++) {
                    unsigned bh[2] = {bfr[j][0].x, bfr[j][1].x};
                    unsigned bl[2] = {bfr[j][0].y, bfr[j][1].y};
                    mma_bf16(acc[i][j], ah, bh);
                    mma_bf16(acc[i][j], ah, bl);
                    mma_bf16(acc[i][j], al, bh);
                }
            }
        }
        __syncthreads();
    }

    // epilogue
    #pragma unroll
    for (int i = 0; i < 4; i++) {
        long long r0 = (long long)rowBase + warpRow + i * 16 + g;
        #pragma unroll
        for (int j = 0; j < 4; j++) {
            int col = warpCol + j * 8 + 2 * q;
            float2 v0 = make_float2(acc[i][j][0], acc[i][j][1]);
            float2 v1 = make_float2(acc[i][j][2], acc[i][j][3]);
            if (!split) {
                if (r0 < NN)     *(float2*)&Csel[(size_t)r0 * 128 + col] = v0;
                if (r0 + 8 < NN) *(float2*)&Csel[(size_t)(r0 + 8) * 128 + col] = v1;
            } else {
                float* Cd; int cc;
                if (col < 64) { Cd = C0; cc = col; } else { Cd = C1; cc = col - 64; }
                if (r0 < NN)     *(float2*)&Cd[(size_t)r0 * 64 + cc] = v0;
                if (r0 + 8 < NN) *(float2*)&Cd[(size_t)(r0 + 8) * 64 + cc] = v1;
            }
        }
    }
}

// ---------------- dtype detection: int64 vs int32 edge_index ----------------
__global__ void k_detect(const int* __restrict__ ebuf) {
    int v = ebuf[2 * threadIdx.x + 1];
    int any = __syncthreads_or(v != 0);
    if (threadIdx.x == 0) g_is64 = any ? 0 : 1;
}

__global__ void k_zero_cnt() {
    int i = blockIdx.x * blockDim.x + threadIdx.x;
    if (i < NN) g_cnt[i] = 0;
}

__device__ __forceinline__ int edge_at(const void* ebuf, int is64, long long idx) {
    if (is64) return (int)((const long long*)ebuf)[idx];
    return ((const int*)ebuf)[idx];
}

__global__ void k_count(const void* __restrict__ ebuf) {
    int e = blockIdx.x * blockDim.x + threadIdx.x;
    if (e >= EE) return;
    int is64 = g_is64;
    int dst = edge_at(ebuf, is64, (long long)EE + e);
    atomicAdd(&g_cnt[dst], 1);
}

__global__ __launch_bounds__(1024) void k_scan1() {
    __shared__ int ws[32];
    int t = threadIdx.x;
    int idx = blockIdx.x * 1024 + t;
    int v = (idx < NN) ? g_cnt[idx] : 0;
    int x = v;
    #pragma unroll
    for (int o = 1; o < 32; o <<= 1) {
        int y = __shfl_up_sync(0xFFFFFFFFu, x, o);
        if ((t & 31) >= o) x += y;
    }
    if ((t & 31) == 31) ws[t >> 5] = x;
    __syncthreads();
    if (t < 32) {
        int w = ws[t];
        #pragma unroll
        for (int o = 1; o < 32; o <<= 1) {
            int y = __shfl_up_sync(0xFFFFFFFFu, w, o);
            if (t >= o) w += y;
        }
        ws[t] = w;
    }
    __syncthreads();
    int prefix = (t >= 32) ? ws[(t >> 5) - 1] : 0;
    int incl = x + prefix;
    if (idx < NN) g_rowptr[idx] = incl - v;
    if (t == 1023) g_bsum[blockIdx.x] = incl;
}

__global__ __launch_bounds__(128) void k_scan2() {
    int t = threadIdx.x;
    int v = (t < NBLK_SCAN) ? g_bsum[t] : 0;
    int x = v;
    #pragma unroll
    for (int o = 1; o < 32; o <<= 1) {
        int y = __shfl_up_sync(0xFFFFFFFFu, x, o);
        if ((t & 31) >= o) x += y;
    }
    __shared__ int ws[4];
    if ((t & 31) == 31) ws[t >> 5] = x;
    __syncthreads();
    if (t < 4) {
        int w = ws[t];
        #pragma unroll
        for (int o = 1; o < 4; o <<= 1) {
            int y = __shfl_up_sync(0xFu, w, o);
            if (t >= o) w += y;
        }
        ws[t] = w;
    }
    __syncthreads();
    int prefix = (t >= 32) ? ws[(t >> 5) - 1] : 0;
    if (t < NBLK_SCAN) g_bsumx[t] = x + prefix - v;
}

__global__ __launch_bounds__(1024) void k_scan3() {
    int t = threadIdx.x;
    int idx = blockIdx.x * 1024 + t;
    int off = g_bsumx[blockIdx.x];
    if (idx < NN) {
        int r = g_rowptr[idx] + off;
        g_rowptr[idx] = r;
        g_cursor[idx] = r;
    }
    if (idx == 0) g_rowptr[NN] = EE;
}

__global__ void k_fill(const void* __restrict__ ebuf) {
    int e = blockIdx.x * blockDim.x + threadIdx.x;
    if (e >= EE) return;
    int is64 = g_is64;
    int src = edge_at(ebuf, is64, e);
    int dst = edge_at(ebuf, is64, (long long)EE + e);
    int pos = atomicAdd(&g_cursor[dst], 1);
    g_col[pos] = src;
}

// ---------------- aggregation layer 1: h = relu(sum y[src] + b1 + z) --------
__global__ __launch_bounds__(256) void k_agg1(const float* __restrict__ b1) {
    int node = blockIdx.x * (blockDim.x / 32) + (threadIdx.x >> 5);
    if (node >= NN) return;
    int lane = threadIdx.x & 31;
    int beg = g_rowptr[node], end = g_rowptr[node + 1];
    float4 bv = *(const float4*)&b1[lane * 4];
    float4 zv = *(const float4*)&g_z[(size_t)node * 128 + lane * 4];
    float4 acc = make_float4(bv.x + zv.x, bv.y + zv.y, bv.z + zv.z, bv.w + zv.w);
    for (int p = beg; p < end; p++) {
        int s = g_col[p];
        float4 v = *(const float4*)&g_y[(size_t)s * 128 + lane * 4];
        acc.x += v.x; acc.y += v.y; acc.z += v.z; acc.w += v.w;
    }
    acc.x = fmaxf(acc.x, 0.f); acc.y = fmaxf(acc.y, 0.f);
    acc.z = fmaxf(acc.z, 0.f); acc.w = fmaxf(acc.w, 0.f);
    uint2 s0 = split2(acc.x, acc.y);
    uint2 s1 = split2(acc.z, acc.w);
    *(uint4*)&g_hs[(size_t)node * 64 + lane * 2] = make_uint4(s0.x, s0.y, s1.x, s1.y);
}

// ---------------- aggregation layer 2: out = sum p[src] + b2 + q ------------
__global__ __launch_bounds__(256) void k_agg2(const float* __restrict__ b2,
                                              float* __restrict__ out) {
    int node = blockIdx.x * (blockDim.x / 32) + (threadIdx.x >> 5);
    if (node >= NN) return;
    int lane = threadIdx.x & 31;
    int beg = g_rowptr[node], end = g_rowptr[node + 1];
    float2 bv = *(const float2*)&b2[lane * 2];
    float2 qv = *(const float2*)&g_q[(size_t)node * 64 + lane * 2];
    float2 acc = make_float2(bv.x + qv.x, bv.y + qv.y);
    for (int p = beg; p < end; p++) {
        int s = g_col[p];
        float2 v = *(const float2*)&g_p[(size_t)s * 64 + lane * 2];
        acc.x += v.x; acc.y += v.y;
    }
    *(float2*)&out[(size_t)node * 64 + lane * 2] = acc;
}

// ---------------- launch -----------------------------------------------------
extern "C" void kernel_launch(void* const* d_in, const int* in_sizes, int n_in,
                              void* d_out, int out_size) {
    (void)in_sizes; (void)n_in; (void)out_size;
    const float* x   = (const float*)d_in[0];
    const void*  ei  = d_in[1];
    const float* w1r = (const float*)d_in[2];
    const float* b1  = (const float*)d_in[3];
    const float* w1o = (const float*)d_in[4];
    const float* w2r = (const float*)d_in[5];
    const float* b2  = (const float*)d_in[6];
    const float* w2o = (const float*)d_in[7];
    float* out = (float*)d_out;

    float *yp, *zp, *pp, *qp;
    uint2 *xsp, *hsp, *w1sp, *w2sp;
    cudaGetSymbolAddress((void**)&yp, g_y);
    cudaGetSymbolAddress((void**)&zp, g_z);
    cudaGetSymbolAddress((void**)&pp, g_p);
    cudaGetSymbolAddress((void**)&qp, g_q);
    cudaGetSymbolAddress((void**)&xsp, g_xs);
    cudaGetSymbolAddress((void**)&hsp, g_hs);
    cudaGetSymbolAddress((void**)&w1sp, g_w1s);
    cudaGetSymbolAddress((void**)&w2sp, g_w2s);

    const int SMEMB = 10240 * 8;     // 80KB dynamic smem
    cudaFuncSetAttribute(k_gemm_pre, cudaFuncAttributeMaxDynamicSharedMemorySize, SMEMB);

    const int EB = (EE + 255) / 256;
    const int NB = (NN + 255) / 256;
    const int AB = (NN + 7) / 8;
    const int XB = (NN * 32 + 255) / 256;

    // launches 0-2: pre-splits
    k_split_x<<<XB, 256>>>(x);
    k_split_w1<<<(2 * 128 * 64 + 255) / 256, 256>>>(w1r, w1o);
    k_split_w2<<<(128 * 64 + 255) / 256, 256>>>(w2r, w2o);

    // launch 3: GEMM1 (positioned here so ncu's capture slot profiles it)
    k_gemm_pre<<<dim3(TILES, 2), 256, SMEMB>>>(xsp, w1sp, w1sp + 128 * 64, yp, zp, 0);

    // CSR build
    k_detect<<<1, 256>>>((const int*)ei);
    k_zero_cnt<<<NB, 256>>>();
    k_count<<<EB, 256>>>(ei);
    k_scan1<<<NBLK_SCAN, 1024>>>();
    k_scan2<<<1, 128>>>();
    k_scan3<<<NBLK_SCAN, 1024>>>();
    k_fill<<<EB, 256>>>(ei);

    // layer 1 aggregation (writes pre-split h)
    k_agg1<<<AB, 256>>>(b1);

    // layer 2
    k_gemm_pre<<<dim3(TILES, 1), 256, SMEMB>>>(hsp, w2sp, w2sp, pp, qp, 1);
    k_agg2<<<AB, 256>>>(b2, out);
}

// round 10
// speedup vs baseline: 1.7437x; 1.0493x over previous
#include <cuda_runtime.h>
#include <cuda_bf16.h>
#include <cuda_fp16.h>
#include <cstdint>

#define NN 100000
#define EE 1600000
#define TILES 782                        // ceil(NN/128)
#define NROWS_PAD ((size_t)TILES * 128)  // 100096
#define NBLK_SCAN ((NN + 1023) / 1024)   // 98

// ---------------- scratch (device globals; no allocations allowed) ----------
__device__ __align__(16) uint2 g_xs[NROWS_PAD * 64];
__device__ __align__(16) uint2 g_hs[NROWS_PAD * 64];
__device__ __align__(16) uint2 g_w1s[2 * 128 * 64];
__device__ __align__(16) uint2 g_w2s[128 * 64];
__device__ __align__(16) __half g_yh[(size_t)NN * 128];  // y in fp16 (gathered)
__device__ __align__(16) __half g_ph[(size_t)NN * 64];   // p in fp16 (gathered)
__device__ float g_z[(size_t)NN * 128];                   // root terms stay fp32
__device__ float g_q[(size_t)NN * 64];
__device__ int   g_rowptr[NN + 1];
__device__ int   g_cnt[NN];
__device__ int   g_cursor[NN];
__device__ int   g_col[EE];
__device__ int   g_is64;
__device__ int   g_bsum[NBLK_SCAN + 32];
__device__ int   g_bsumx[NBLK_SCAN + 32];

// ---------------- helpers ----------------------------------------------------
__device__ __forceinline__ uint2 split2(float a, float b) {
    __nv_bfloat16 ha = __float2bfloat16(a), hb = __float2bfloat16(b);
    float ra = a - __bfloat162float(ha);
    float rb = b - __bfloat162float(hb);
    __nv_bfloat162 H = __halves2bfloat162(ha, hb);
    __nv_bfloat162 L = __floats2bfloat162_rn(ra, rb);
    uint2 r;
    r.x = *reinterpret_cast<unsigned*>(&H);
    r.y = *reinterpret_cast<unsigned*>(&L);
    return r;
}

__device__ __forceinline__ void mma_bf16(float* c, const unsigned* a, const unsigned* b) {
    asm volatile(
        "mma.sync.aligned.m16n8k16.row.col.f32.bf16.bf16.f32 "
        "{%0,%1,%2,%3}, {%4,%5,%6,%7}, {%8,%9}, {%0,%1,%2,%3};\n"
        : "+f"(c[0]), "+f"(c[1]), "+f"(c[2]), "+f"(c[3])
        : "r"(a[0]), "r"(a[1]), "r"(a[2]), "r"(a[3]), "r"(b[0]), "r"(b[1]));
}

__device__ __forceinline__ void cp16(uint32_t dst, const void* src) {
    asm volatile("cp.async.cg.shared.global [%0], [%1], 16;\n"
                 :: "r"(dst), "l"(__cvta_generic_to_global(src)) : "memory");
}

// ---------------- pre-split kernels ------------------------------------------
__global__ __launch_bounds__(256) void k_split_x(const float* __restrict__ x) {
    int idx = blockIdx.x * blockDim.x + threadIdx.x;
    if (idx >= NN * 32) return;
    int row = idx >> 5, q4 = idx & 31;
    float4 v = *(const float4*)&x[(size_t)row * 128 + q4 * 4];
    uint2 s0 = split2(v.x, v.y);
    uint2 s1 = split2(v.z, v.w);
    *(uint4*)&g_xs[(size_t)row * 64 + q4 * 2] = make_uint4(s0.x, s0.y, s1.x, s1.y);
}

__global__ __launch_bounds__(256) void k_split_w1(const float* __restrict__ w1r,
                                                  const float* __restrict__ w1o) {
    int idx = blockIdx.x * blockDim.x + threadIdx.x;
    if (idx >= 2 * 128 * 64) return;
    int sel = idx >> 13;
    int rem = idx & 8191;
    int col = rem >> 6, kw = rem & 63;
    const float* W = sel ? w1o : w1r;
    g_w1s[idx] = split2(W[(size_t)(2 * kw) * 128 + col],
                        W[(size_t)(2 * kw + 1) * 128 + col]);
}

__global__ __launch_bounds__(256) void k_split_w2(const float* __restrict__ w2r,
                                                  const float* __restrict__ w2o) {
    int idx = blockIdx.x * blockDim.x + threadIdx.x;
    if (idx >= 128 * 64) return;
    int col = idx >> 6, kw = idx & 63;
    const float* W = (col < 64) ? w2r : w2o;
    int c = col & 63;
    g_w2s[idx] = split2(W[(size_t)(2 * kw) * 64 + c],
                        W[(size_t)(2 * kw + 1) * 64 + c]);
}

// ---------------- 3xBF16 mma.sync GEMM, cp.async double-buffered -------------
// Gathered outputs (y, p) stored fp16; root outputs (z, q) stored fp32.
__global__ __launch_bounds__(256, 2) void k_gemm_pre(
    const uint2* __restrict__ A,
    const uint2* __restrict__ B0, const uint2* __restrict__ B1,
    __half* __restrict__ H0, float* __restrict__ F1,
    int split)
{
    extern __shared__ __align__(16) uint2 sm[];
    uint32_t sbase = (uint32_t)__cvta_generic_to_shared(sm);

    int tid = threadIdx.x;
    int wid = tid >> 5, lane = tid & 31;
    int g = lane >> 2, q = lane & 3;
    int warpRow = (wid >> 2) * 64;
    int warpCol = (wid & 3) * 32;
    size_t rowBase = (size_t)blockIdx.x * 128;

    const uint2* Bsel = (!split) ? ((blockIdx.y == 0) ? B0 : B1) : B0;

    float acc[4][4][4];
    #pragma unroll
    for (int i = 0; i < 4; i++)
        #pragma unroll
        for (int j = 0; j < 4; j++)
            #pragma unroll
            for (int r = 0; r < 4; r++) acc[i][j][r] = 0.f;

    auto copy_chunk = [&](int c, int stage) {
        int k0w = c * 16;
        #pragma unroll
        for (int it = 0; it < 4; it++) {
            int s = it * 256 + tid;
            int kw2 = s & 7;
            int row = s >> 3;
            uint32_t dst = sbase + (uint32_t)((stage * 2560 + row * 20 + kw2 * 2) * 8);
            cp16(dst, &A[(rowBase + row) * 64 + k0w + kw2 * 2]);
        }
        #pragma unroll
        for (int it = 0; it < 4; it++) {
            int s = it * 256 + tid;
            int kw2 = s & 7;
            int col = s >> 3;
            uint32_t dst = sbase + (uint32_t)((5120 + stage * 2560 + col * 20 + kw2 * 2) * 8);
            cp16(dst, &Bsel[(size_t)col * 64 + k0w + kw2 * 2]);
        }
        asm volatile("cp.async.commit_group;\n" ::: "memory");
    };

    copy_chunk(0, 0);

    for (int c = 0; c < 4; c++) {
        int stage = c & 1;
        if (c + 1 < 4) {
            copy_chunk(c + 1, (c + 1) & 1);
            asm volatile("cp.async.wait_group 1;\n" ::: "memory");
        } else {
            asm volatile("cp.async.wait_group 0;\n" ::: "memory");
        }
        __syncthreads();

        uint2 (*As)[20] = (uint2(*)[20])(sm + stage * 2560);
        uint2 (*Bs)[20] = (uint2(*)[20])(sm + 5120 + stage * 2560);

        #pragma unroll
        for (int t = 0; t < 2; t++) {
            int p0 = t * 8 + q, p1 = p0 + 4;
            uint2 bfr[4][2];
            #pragma unroll
            for (int j = 0; j < 4; j++) {
                int col = warpCol + j * 8 + g;
                bfr[j][0] = Bs[col][p0];
                bfr[j][1] = Bs[col][p1];
            }
            #pragma unroll
            for (int i = 0; i < 4; i++) {
                int r0 = warpRow + i * 16 + g;
                uint2 a0 = As[r0][p0], a1 = As[r0 + 8][p0];
                uint2 a2 = As[r0][p1], a3 = As[r0 + 8][p1];
                unsigned ah[4] = {a0.x, a1.x, a2.x, a3.x};
                unsigned al[4] = {a0.y, a1.y, a2.y, a3.y};
                #pragma unroll
                for (int j = 0; j < 4; j++) {
                    unsigned bh[2] = {bfr[j][0].x, bfr[j][1].x};
                    unsigned bl[2] = {bfr[j][0].y, bfr[j][1].y};
                    mma_bf16(acc[i][j], ah, bh);
                    mma_bf16(acc[i][j], ah, bl);
                    mma_bf16(acc[i][j], al, bh);
                }
            }
        }
        __syncthreads();
    }

    // epilogue: fp16 for gathered outputs, fp32 for root outputs
    #pragma unroll
    for (int i = 0; i < 4; i++) {
        long long r0 = (long long)rowBase + warpRow + i * 16 + g;
        #pragma unroll
        for (int j = 0; j < 4; j++) {
            int col = warpCol + j * 8 + 2 * q;
            if (!split) {
                if (blockIdx.y == 0) {   // y -> fp16, width 128
                    __half2 h0 = __floats2half2_rn(acc[i][j][0], acc[i][j][1]);
                    __half2 h1 = __floats2half2_rn(acc[i][j][2], acc[i][j][3]);
                    if (r0 < NN)     *(__half2*)&H0[(size_t)r0 * 128 + col] = h0;
                    if (r0 + 8 < NN) *(__half2*)&H0[(size_t)(r0 + 8) * 128 + col] = h1;
                } else {                 // z -> fp32, width 128
                    if (r0 < NN)
                        *(float2*)&F1[(size_t)r0 * 128 + col] =
                            make_float2(acc[i][j][0], acc[i][j][1]);
                    if (r0 + 8 < NN)
                        *(float2*)&F1[(size_t)(r0 + 8) * 128 + col] =
                            make_float2(acc[i][j][2], acc[i][j][3]);
                }
            } else {
                if (col < 64) {          // p -> fp16, width 64
                    __half2 h0 = __floats2half2_rn(acc[i][j][0], acc[i][j][1]);
                    __half2 h1 = __floats2half2_rn(acc[i][j][2], acc[i][j][3]);
                    if (r0 < NN)     *(__half2*)&H0[(size_t)r0 * 64 + col] = h0;
                    if (r0 + 8 < NN) *(__half2*)&H0[(size_t)(r0 + 8) * 64 + col] = h1;
                } else {                 // q -> fp32, width 64
                    int cc = col - 64;
                    if (r0 < NN)
                        *(float2*)&F1[(size_t)r0 * 64 + cc] =
                            make_float2(acc[i][j][0], acc[i][j][1]);
                    if (r0 + 8 < NN)
                        *(float2*)&F1[(size_t)(r0 + 8) * 64 + cc] =
                            make_float2(acc[i][j][2], acc[i][j][3]);
                }
            }
        }
    }
}

// ---------------- dtype detection: int64 vs int32 edge_index ----------------
__global__ void k_detect(const int* __restrict__ ebuf) {
    int v = ebuf[2 * threadIdx.x + 1];
    int any = __syncthreads_or(v != 0);
    if (threadIdx.x == 0) g_is64 = any ? 0 : 1;
}

__global__ void k_zero_cnt() {
    int i = blockIdx.x * blockDim.x + threadIdx.x;
    if (i < NN) g_cnt[i] = 0;
}

__device__ __forceinline__ int edge_at(const void* ebuf, int is64, long long idx) {
    if (is64) return (int)((const long long*)ebuf)[idx];
    return ((const int*)ebuf)[idx];
}

__global__ void k_count(const void* __restrict__ ebuf) {
    int e = blockIdx.x * blockDim.x + threadIdx.x;
    if (e >= EE) return;
    int is64 = g_is64;
    int dst = edge_at(ebuf, is64, (long long)EE + e);
    atomicAdd(&g_cnt[dst], 1);
}

__global__ __launch_bounds__(1024) void k_scan1() {
    __shared__ int ws[32];
    int t = threadIdx.x;
    int idx = blockIdx.x * 1024 + t;
    int v = (idx < NN) ? g_cnt[idx] : 0;
    int x = v;
    #pragma unroll
    for (int o = 1; o < 32; o <<= 1) {
        int y = __shfl_up_sync(0xFFFFFFFFu, x, o);
        if ((t & 31) >= o) x += y;
    }
    if ((t & 31) == 31) ws[t >> 5] = x;
    __syncthreads();
    if (t < 32) {
        int w = ws[t];
        #pragma unroll
        for (int o = 1; o < 32; o <<= 1) {
            int y = __shfl_up_sync(0xFFFFFFFFu, w, o);
            if (t >= o) w += y;
        }
        ws[t] = w;
    }
    __syncthreads();
    int prefix = (t >= 32) ? ws[(t >> 5) - 1] : 0;
    int incl = x + prefix;
    if (idx < NN) g_rowptr[idx] = incl - v;
    if (t == 1023) g_bsum[blockIdx.x] = incl;
}

__global__ __launch_bounds__(128) void k_scan2() {
    int t = threadIdx.x;
    int v = (t < NBLK_SCAN) ? g_bsum[t] : 0;
    int x = v;
    #pragma unroll
    for (int o = 1; o < 32; o <<= 1) {
        int y = __shfl_up_sync(0xFFFFFFFFu, x, o);
        if ((t & 31) >= o) x += y;
    }
    __shared__ int ws[4];
    if ((t & 31) == 31) ws[t >> 5] = x;
    __syncthreads();
    if (t < 4) {
        int w = ws[t];
        #pragma unroll
        for (int o = 1; o < 4; o <<= 1) {
            int y = __shfl_up_sync(0xFu, w, o);
            if (t >= o) w += y;
        }
        ws[t] = w;
    }
    __syncthreads();
    int prefix = (t >= 32) ? ws[(t >> 5) - 1] : 0;
    if (t < NBLK_SCAN) g_bsumx[t] = x + prefix - v;
}

__global__ __launch_bounds__(1024) void k_scan3() {
    int t = threadIdx.x;
    int idx = blockIdx.x * 1024 + t;
    int off = g_bsumx[blockIdx.x];
    if (idx < NN) {
        int r = g_rowptr[idx] + off;
        g_rowptr[idx] = r;
        g_cursor[idx] = r;
    }
    if (idx == 0) g_rowptr[NN] = EE;
}

__global__ void k_fill(const void* __restrict__ ebuf) {
    int e = blockIdx.x * blockDim.x + threadIdx.x;
    if (e >= EE) return;
    int is64 = g_is64;
    int src = edge_at(ebuf, is64, e);
    int dst = edge_at(ebuf, is64, (long long)EE + e);
    int pos = atomicAdd(&g_cursor[dst], 1);
    g_col[pos] = src;
}

// ---------------- aggregation layer 1: h = relu(sum y[src] + b1 + z) --------
__global__ __launch_bounds__(256) void k_agg1(const float* __restrict__ b1) {
    int node = blockIdx.x * (blockDim.x / 32) + (threadIdx.x >> 5);
    if (node >= NN) return;
    int lane = threadIdx.x & 31;
    int beg = g_rowptr[node], end = g_rowptr[node + 1];
    float4 bv = *(const float4*)&b1[lane * 4];
    float4 zv = *(const float4*)&g_z[(size_t)node * 128 + lane * 4];
    float4 acc = make_float4(bv.x + zv.x, bv.y + zv.y, bv.z + zv.z, bv.w + zv.w);
    for (int p = beg; p < end; p++) {
        int s = g_col[p];
        uint2 v = *(const uint2*)&g_yh[(size_t)s * 128 + lane * 4];
        float2 f0 = __half22float2(*reinterpret_cast<__half2*>(&v.x));
        float2 f1 = __half22float2(*reinterpret_cast<__half2*>(&v.y));
        acc.x += f0.x; acc.y += f0.y; acc.z += f1.x; acc.w += f1.y;
    }
    acc.x = fmaxf(acc.x, 0.f); acc.y = fmaxf(acc.y, 0.f);
    acc.z = fmaxf(acc.z, 0.f); acc.w = fmaxf(acc.w, 0.f);
    uint2 s0 = split2(acc.x, acc.y);
    uint2 s1 = split2(acc.z, acc.w);
    *(uint4*)&g_hs[(size_t)node * 64 + lane * 2] = make_uint4(s0.x, s0.y, s1.x, s1.y);
}

// ---------------- aggregation layer 2: out = sum p[src] + b2 + q ------------
__global__ __launch_bounds__(256) void k_agg2(const float* __restrict__ b2,
                                              float* __restrict__ out) {
    int node = blockIdx.x * (blockDim.x / 32) + (threadIdx.x >> 5);
    if (node >= NN) return;
    int lane = threadIdx.x & 31;
    int beg = g_rowptr[node], end = g_rowptr[node + 1];
    float2 bv = *(const float2*)&b2[lane * 2];
    float2 qv = *(const float2*)&g_q[(size_t)node * 64 + lane * 2];
    float2 acc = make_float2(bv.x + qv.x, bv.y + qv.y);
    for (int p = beg; p < end; p++) {
        int s = g_col[p];
        unsigned v = *(const unsigned*)&g_ph[(size_t)s * 64 + lane * 2];
        float2 f = __half22float2(*reinterpret_cast<__half2*>(&v));
        acc.x += f.x; acc.y += f.y;
    }
    *(float2*)&out[(size_t)node * 64 + lane * 2] = acc;
}

// ---------------- launch -----------------------------------------------------
extern "C" void kernel_launch(void* const* d_in, const int* in_sizes, int n_in,
                              void* d_out, int out_size) {
    (void)in_sizes; (void)n_in; (void)out_size;
    const float* x   = (const float*)d_in[0];
    const void*  ei  = d_in[1];
    const float* w1r = (const float*)d_in[2];
    const float* b1  = (const float*)d_in[3];
    const float* w1o = (const float*)d_in[4];
    const float* w2r = (const float*)d_in[5];
    const float* b2  = (const float*)d_in[6];
    const float* w2o = (const float*)d_in[7];
    float* out = (float*)d_out;

    float *zp, *qp;
    __half *yhp, *php;
    uint2 *xsp, *hsp, *w1sp, *w2sp;
    cudaGetSymbolAddress((void**)&zp, g_z);
    cudaGetSymbolAddress((void**)&qp, g_q);
    cudaGetSymbolAddress((void**)&yhp, g_yh);
    cudaGetSymbolAddress((void**)&php, g_ph);
    cudaGetSymbolAddress((void**)&xsp, g_xs);
    cudaGetSymbolAddress((void**)&hsp, g_hs);
    cudaGetSymbolAddress((void**)&w1sp, g_w1s);
    cudaGetSymbolAddress((void**)&w2sp, g_w2s);

    const int SMEMB = 10240 * 8;     // 80KB dynamic smem
    cudaFuncSetAttribute(k_gemm_pre, cudaFuncAttributeMaxDynamicSharedMemorySize, SMEMB);

    const int EB = (EE + 255) / 256;
    const int NB = (NN + 255) / 256;
    const int AB = (NN + 7) / 8;
    const int XB = (NN * 32 + 255) / 256;

    // pre-splits
    k_split_x<<<XB, 256>>>(x);
    k_split_w1<<<(2 * 128 * 64 + 255) / 256, 256>>>(w1r, w1o);
    k_split_w2<<<(128 * 64 + 255) / 256, 256>>>(w2r, w2o);

    // GEMM1 (launch slot ncu captures)
    k_gemm_pre<<<dim3(TILES, 2), 256, SMEMB>>>(xsp, w1sp, w1sp + 128 * 64, yhp, zp, 0);

    // CSR build
    k_detect<<<1, 256>>>((const int*)ei);
    k_zero_cnt<<<NB, 256>>>();
    k_count<<<EB, 256>>>(ei);
    k_scan1<<<NBLK_SCAN, 1024>>>();
    k_scan2<<<1, 128>>>();
    k_scan3<<<NBLK_SCAN, 1024>>>();
    k_fill<<<EB, 256>>>(ei);

    // layer 1 aggregation (fp16 gather, writes pre-split h)
    k_agg1<<<AB, 256>>>(b1);

    // layer 2
    k_gemm_pre<<<dim3(TILES, 1), 256, SMEMB>>>(hsp, w2sp, w2sp, php, qp, 1);
    k_agg2<<<AB, 256>>>(b2, out);
}

// round 12
// speedup vs baseline: 2.4064x; 1.3800x over previous
#include <cuda_runtime.h>
#include <cuda_fp16.h>
#include <cstdint>

#define NN 100000
#define EE 1600000
#define TILES 782                        // ceil(NN/128)
#define NROWS_PAD ((size_t)TILES * 128)  // 100096
#define NBLK_SCAN ((NN + 1023) / 1024)   // 98

// ---------------- scratch (device globals; no allocations allowed) ----------
// fp16 operand images: [row][64 words], word = half2 (k=2w, 2w+1). Padded rows zero.
__device__ __align__(16) unsigned g_xh[NROWS_PAD * 64];
__device__ __align__(16) unsigned g_hh[NROWS_PAD * 64];
__device__ __align__(16) unsigned g_w1h[2 * 128 * 64];  // [sel][col][kword]
__device__ __align__(16) unsigned g_w2h[128 * 64];      // [col][kword] (cols 0-63 w2r)
__device__ __align__(16) __half g_yh[(size_t)NN * 128]; // y fp16 (gathered)
__device__ __align__(16) __half g_ph[(size_t)NN * 64];  // p fp16 (gathered)
__device__ float g_z[(size_t)NN * 128];                  // root terms fp32
__device__ float g_q[(size_t)NN * 64];
__device__ int   g_rowptr[NN + 1];
__device__ int   g_cnt[NN];
__device__ int   g_cursor[NN];
__device__ int   g_col[EE];
__device__ int   g_is64;
__device__ int   g_bsum[NBLK_SCAN + 32];
__device__ int   g_bsumx[NBLK_SCAN + 32];

// ---------------- helpers ----------------------------------------------------
__device__ __forceinline__ unsigned pack2(float a, float b) {
    __half2 h = __floats2half2_rn(a, b);
    return *reinterpret_cast<unsigned*>(&h);
}

__device__ __forceinline__ void mma_f16(float* c, const unsigned* a, const unsigned* b) {
    asm volatile(
        "mma.sync.aligned.m16n8k16.row.col.f32.f16.f16.f32 "
        "{%0,%1,%2,%3}, {%4,%5,%6,%7}, {%8,%9}, {%0,%1,%2,%3};\n"
        : "+f"(c[0]), "+f"(c[1]), "+f"(c[2]), "+f"(c[3])
        : "r"(a[0]), "r"(a[1]), "r"(a[2]), "r"(a[3]), "r"(b[0]), "r"(b[1]));
}

__device__ __forceinline__ void cp16(uint32_t dst, const void* src) {
    asm volatile("cp.async.cg.shared.global [%0], [%1], 16;\n"
                 :: "r"(dst), "l"(__cvta_generic_to_global(src)) : "memory");
}

// ---------------- pre-split (fp32 -> fp16 image) ------------------------------
__global__ __launch_bounds__(256) void k_split_x(const float* __restrict__ x) {
    int idx = blockIdx.x * blockDim.x + threadIdx.x;   // uint4 task = 8 fp16
    if (idx >= NN * 16) return;
    int row = idx >> 4, q = idx & 15;
    float4 v0 = *(const float4*)&x[(size_t)row * 128 + q * 8];
    float4 v1 = *(const float4*)&x[(size_t)row * 128 + q * 8 + 4];
    uint4 pk = make_uint4(pack2(v0.x, v0.y), pack2(v0.z, v0.w),
                          pack2(v1.x, v1.y), pack2(v1.z, v1.w));
    *(uint4*)&g_xh[(size_t)row * 64 + q * 4] = pk;
}

__global__ __launch_bounds__(256) void k_split_w1(const float* __restrict__ w1r,
                                                  const float* __restrict__ w1o) {
    int idx = blockIdx.x * blockDim.x + threadIdx.x;
    if (idx >= 2 * 128 * 64) return;
    int sel = idx >> 13;
    int rem = idx & 8191;
    int col = rem >> 6, kw = rem & 63;
    const float* W = sel ? w1o : w1r;
    g_w1h[idx] = pack2(W[(size_t)(2 * kw) * 128 + col],
                       W[(size_t)(2 * kw + 1) * 128 + col]);
}

__global__ __launch_bounds__(256) void k_split_w2(const float* __restrict__ w2r,
                                                  const float* __restrict__ w2o) {
    int idx = blockIdx.x * blockDim.x + threadIdx.x;
    if (idx >= 128 * 64) return;
    int col = idx >> 6, kw = idx & 63;
    const float* W = (col < 64) ? w2r : w2o;
    int c = col & 63;
    g_w2h[idx] = pack2(W[(size_t)(2 * kw) * 64 + c],
                       W[(size_t)(2 * kw + 1) * 64 + c]);
}

// ---------------- fp16 mma.sync GEMM, cp.async double-buffered ----------------
// smem (32-bit words): As[stage] at stage*2560 (128 rows x stride 20),
//                      Bs[stage] at 5120 + stage*2560. Total 10240 words = 40KB.
// Stride 20 words/row: frag LDS (8 rows x words {q, q+4}) hits 32 distinct banks.
__global__ __launch_bounds__(256, 2) void k_gemm_f16(
    const unsigned* __restrict__ A,
    const unsigned* __restrict__ B0, const unsigned* __restrict__ B1,
    __half* __restrict__ H0, float* __restrict__ F1,
    int split)
{
    extern __shared__ __align__(16) unsigned sm[];
    uint32_t sbase = (uint32_t)__cvta_generic_to_shared(sm);

    int tid = threadIdx.x;
    int wid = tid >> 5, lane = tid & 31;
    int g = lane >> 2, q = lane & 3;
    int warpRow = (wid >> 2) * 64;
    int warpCol = (wid & 3) * 32;
    size_t rowBase = (size_t)blockIdx.x * 128;

    const unsigned* Bsel = (!split) ? ((blockIdx.y == 0) ? B0 : B1) : B0;

    float acc[4][4][4];
    #pragma unroll
    for (int i = 0; i < 4; i++)
        #pragma unroll
        for (int j = 0; j < 4; j++)
            #pragma unroll
            for (int r = 0; r < 4; r++) acc[i][j][r] = 0.f;

    // one chunk = k-words [c*16, c*16+16) for all 128 rows/cols: 512 cp16 each
    auto copy_chunk = [&](int c, int stage) {
        #pragma unroll
        for (int it = 0; it < 2; it++) {
            int s = it * 256 + tid;
            int row = s >> 2, qd = s & 3;
            uint32_t dst = sbase + (uint32_t)((stage * 2560 + row * 20 + qd * 4) * 4);
            cp16(dst, &A[(rowBase + row) * 64 + c * 16 + qd * 4]);
        }
        #pragma unroll
        for (int it = 0; it < 2; it++) {
            int s = it * 256 + tid;
            int col = s >> 2, qd = s & 3;
            uint32_t dst = sbase + (uint32_t)((5120 + stage * 2560 + col * 20 + qd * 4) * 4);
            cp16(dst, &Bsel[(size_t)col * 64 + c * 16 + qd * 4]);
        }
        asm volatile("cp.async.commit_group;\n" ::: "memory");
    };

    copy_chunk(0, 0);

    for (int c = 0; c < 4; c++) {
        int stage = c & 1;
        if (c + 1 < 4) {
            copy_chunk(c + 1, (c + 1) & 1);
            asm volatile("cp.async.wait_group 1;\n" ::: "memory");
        } else {
            asm volatile("cp.async.wait_group 0;\n" ::: "memory");
        }
        __syncthreads();

        const unsigned* As = sm + stage * 2560;
        const unsigned* Bs = sm + 5120 + stage * 2560;

        #pragma unroll
        for (int t = 0; t < 2; t++) {          // two k16 steps per 32-k chunk
            int kb = t * 8;
            unsigned bfr[4][2];
            #pragma unroll
            for (int j = 0; j < 4; j++) {
                int col = warpCol + j * 8 + g;
                bfr[j][0] = Bs[col * 20 + kb + q];
                bfr[j][1] = Bs[col * 20 + kb + q + 4];
            }
            #pragma unroll
            for (int i = 0; i < 4; i++) {
                int r0 = warpRow + i * 16 + g;
                unsigned af[4];
                af[0] = As[r0 * 20 + kb + q];
                af[1] = As[(r0 + 8) * 20 + kb + q];
                af[2] = As[r0 * 20 + kb + q + 4];
                af[3] = As[(r0 + 8) * 20 + kb + q + 4];
                #pragma unroll
                for (int j = 0; j < 4; j++)
                    mma_f16(acc[i][j], af, bfr[j]);
            }
        }
        __syncthreads();
    }

    // epilogue: fp16 for gathered outputs (y/p), fp32 for root outputs (z/q)
    #pragma unroll
    for (int i = 0; i < 4; i++) {
        long long r0 = (long long)rowBase + warpRow + i * 16 + g;
        #pragma unroll
        for (int j = 0; j < 4; j++) {
            int col = warpCol + j * 8 + 2 * q;
            if (!split) {
                if (blockIdx.y == 0) {   // y -> fp16, width 128
                    __half2 h0 = __floats2half2_rn(acc[i][j][0], acc[i][j][1]);
                    __half2 h1 = __floats2half2_rn(acc[i][j][2], acc[i][j][3]);
                    if (r0 < NN)     *(__half2*)&H0[(size_t)r0 * 128 + col] = h0;
                    if (r0 + 8 < NN) *(__half2*)&H0[(size_t)(r0 + 8) * 128 + col] = h1;
                } else {                 // z -> fp32, width 128
                    if (r0 < NN)
                        *(float2*)&F1[(size_t)r0 * 128 + col] =
                            make_float2(acc[i][j][0], acc[i][j][1]);
                    if (r0 + 8 < NN)
                        *(float2*)&F1[(size_t)(r0 + 8) * 128 + col] =
                            make_float2(acc[i][j][2], acc[i][j][3]);
                }
            } else {
                if (col < 64) {          // p -> fp16, width 64
                    __half2 h0 = __floats2half2_rn(acc[i][j][0], acc[i][j][1]);
                    __half2 h1 = __floats2half2_rn(acc[i][j][2], acc[i][j][3]);
                    if (r0 < NN)     *(__half2*)&H0[(size_t)r0 * 64 + col] = h0;
                    if (r0 + 8 < NN) *(__half2*)&H0[(size_t)(r0 + 8) * 64 + col] = h1;
                } else {                 // q -> fp32, width 64
                    int cc = col - 64;
                    if (r0 < NN)
                        *(float2*)&F1[(size_t)r0 * 64 + cc] =
                            make_float2(acc[i][j][0], acc[i][j][1]);
                    if (r0 + 8 < NN)
                        *(float2*)&F1[(size_t)(r0 + 8) * 64 + cc] =
                            make_float2(acc[i][j][2], acc[i][j][3]);
                }
            }
        }
    }
}

// ---------------- dtype detection: int64 vs int32 edge_index ----------------
__global__ void k_detect(const int* __restrict__ ebuf) {
    int v = ebuf[2 * threadIdx.x + 1];
    int any = __syncthreads_or(v != 0);
    if (threadIdx.x == 0) g_is64 = any ? 0 : 1;
}

__global__ void k_zero_cnt() {
    int i = blockIdx.x * blockDim.x + threadIdx.x;
    if (i < NN) g_cnt[i] = 0;
}

__device__ __forceinline__ int edge_at(const void* ebuf, int is64, long long idx) {
    if (is64) return (int)((const long long*)ebuf)[idx];
    return ((const int*)ebuf)[idx];
}

__global__ void k_count(const void* __restrict__ ebuf) {
    int e = blockIdx.x * blockDim.x + threadIdx.x;
    if (e >= EE) return;
    int is64 = g_is64;
    int dst = edge_at(ebuf, is64, (long long)EE + e);
    atomicAdd(&g_cnt[dst], 1);
}

__global__ __launch_bounds__(1024) void k_scan1() {
    __shared__ int ws[32];
    int t = threadIdx.x;
    int idx = blockIdx.x * 1024 + t;
    int v = (idx < NN) ? g_cnt[idx] : 0;
    int x = v;
    #pragma unroll
    for (int o = 1; o < 32; o <<= 1) {
        int y = __shfl_up_sync(0xFFFFFFFFu, x, o);
        if ((t & 31) >= o) x += y;
    }
    if ((t & 31) == 31) ws[t >> 5] = x;
    __syncthreads();
    if (t < 32) {
        int w = ws[t];
        #pragma unroll
        for (int o = 1; o < 32; o <<= 1) {
            int y = __shfl_up_sync(0xFFFFFFFFu, w, o);
            if (t >= o) w += y;
        }
        ws[t] = w;
    }
    __syncthreads();
    int prefix = (t >= 32) ? ws[(t >> 5) - 1] : 0;
    int incl = x + prefix;
    if (idx < NN) g_rowptr[idx] = incl - v;
    if (t == 1023) g_bsum[blockIdx.x] = incl;
}

__global__ __launch_bounds__(128) void k_scan2() {
    int t = threadIdx.x;
    int v = (t < NBLK_SCAN) ? g_bsum[t] : 0;
    int x = v;
    #pragma unroll
    for (int o = 1; o < 32; o <<= 1) {
        int y = __shfl_up_sync(0xFFFFFFFFu, x, o);
        if ((t & 31) >= o) x += y;
    }
    __shared__ int ws[4];
    if ((t & 31) == 31) ws[t >> 5] = x;
    __syncthreads();
    if (t < 4) {
        int w = ws[t];
        #pragma unroll
        for (int o = 1; o < 4; o <<= 1) {
            int y = __shfl_up_sync(0xFu, w, o);
            if (t >= o) w += y;
        }
        ws[t] = w;
    }
    __syncthreads();
    int prefix = (t >= 32) ? ws[(t >> 5) - 1] : 0;
    if (t < NBLK_SCAN) g_bsumx[t] = x + prefix - v;
}

__global__ __launch_bounds__(1024) void k_scan3() {
    int t = threadIdx.x;
    int idx = blockIdx.x * 1024 + t;
    int off = g_bsumx[blockIdx.x];
    if (idx < NN) {
        int r = g_rowptr[idx] + off;
        g_rowptr[idx] = r;
        g_cursor[idx] = r;
    }
    if (idx == 0) g_rowptr[NN] = EE;
}

__global__ void k_fill(const void* __restrict__ ebuf) {
    int e = blockIdx.x * blockDim.x + threadIdx.x;
    if (e >= EE) return;
    int is64 = g_is64;
    int src = edge_at(ebuf, is64, e);
    int dst = edge_at(ebuf, is64, (long long)EE + e);
    int pos = atomicAdd(&g_cursor[dst], 1);
    g_col[pos] = src;
}

// ---------------- aggregation layer 1: h = relu(sum y[src] + b1 + z) --------
// Writes h directly as fp16 image words for GEMM2.
__global__ __launch_bounds__(256) void k_agg1(const float* __restrict__ b1) {
    int node = blockIdx.x * (blockDim.x / 32) + (threadIdx.x >> 5);
    if (node >= NN) return;
    int lane = threadIdx.x & 31;
    int beg = g_rowptr[node], end = g_rowptr[node + 1];
    float4 bv = *(const float4*)&b1[lane * 4];
    float4 zv = *(const float4*)&g_z[(size_t)node * 128 + lane * 4];
    float4 acc = make_float4(bv.x + zv.x, bv.y + zv.y, bv.z + zv.z, bv.w + zv.w);
    for (int p = beg; p < end; p++) {
        int s = g_col[p];
        uint2 v = *(const uint2*)&g_yh[(size_t)s * 128 + lane * 4];
        float2 f0 = __half22float2(*reinterpret_cast<__half2*>(&v.x));
        float2 f1 = __half22float2(*reinterpret_cast<__half2*>(&v.y));
        acc.x += f0.x; acc.y += f0.y; acc.z += f1.x; acc.w += f1.y;
    }
    acc.x = fmaxf(acc.x, 0.f); acc.y = fmaxf(acc.y, 0.f);
    acc.z = fmaxf(acc.z, 0.f); acc.w = fmaxf(acc.w, 0.f);
    *(uint2*)&g_hh[(size_t)node * 64 + lane * 2] =
        make_uint2(pack2(acc.x, acc.y), pack2(acc.z, acc.w));
}

// ---------------- aggregation layer 2: out = sum p[src] + b2 + q ------------
__global__ __launch_bounds__(256) void k_agg2(const float* __restrict__ b2,
                                              float* __restrict__ out) {
    int node = blockIdx.x * (blockDim.x / 32) + (threadIdx.x >> 5);
    if (node >= NN) return;
    int lane = threadIdx.x & 31;
    int beg = g_rowptr[node], end = g_rowptr[node + 1];
    float2 bv = *(const float2*)&b2[lane * 2];
    float2 qv = *(const float2*)&g_q[(size_t)node * 64 + lane * 2];
    float2 acc = make_float2(bv.x + qv.x, bv.y + qv.y);
    for (int p = beg; p < end; p++) {
        int s = g_col[p];
        unsigned v = *(const unsigned*)&g_ph[(size_t)s * 64 + lane * 2];
        float2 f = __half22float2(*reinterpret_cast<__half2*>(&v));
        acc.x += f.x; acc.y += f.y;
    }
    *(float2*)&out[(size_t)node * 64 + lane * 2] = acc;
}

// ---------------- launch -----------------------------------------------------
extern "C" void kernel_launch(void* const* d_in, const int* in_sizes, int n_in,
                              void* d_out, int out_size) {
    (void)in_sizes; (void)n_in; (void)out_size;
    const float* x   = (const float*)d_in[0];
    const void*  ei  = d_in[1];
    const float* w1r = (const float*)d_in[2];
    const float* b1  = (const float*)d_in[3];
    const float* w1o = (const float*)d_in[4];
    const float* w2r = (const float*)d_in[5];
    const float* b2  = (const float*)d_in[6];
    const float* w2o = (const float*)d_in[7];
    float* out = (float*)d_out;

    float *zp, *qp;
    __half *yhp, *php;
    unsigned *xhp, *hhp, *w1hp, *w2hp;
    cudaGetSymbolAddress((void**)&zp, g_z);
    cudaGetSymbolAddress((void**)&qp, g_q);
    cudaGetSymbolAddress((void**)&yhp, g_yh);
    cudaGetSymbolAddress((void**)&php, g_ph);
    cudaGetSymbolAddress((void**)&xhp, g_xh);
    cudaGetSymbolAddress((void**)&hhp, g_hh);
    cudaGetSymbolAddress((void**)&w1hp, g_w1h);
    cudaGetSymbolAddress((void**)&w2hp, g_w2h);

    const int SMEMB = 10240 * 4;     // 40KB dynamic smem
    cudaFuncSetAttribute(k_gemm_f16, cudaFuncAttributeMaxDynamicSharedMemorySize, SMEMB);

    const int EB = (EE + 255) / 256;
    const int NB = (NN + 255) / 256;
    const int AB = (NN + 7) / 8;
    const int XB = (NN * 16 + 255) / 256;

    // pre-splits (fp16 images)
    k_split_x<<<XB, 256>>>(x);
    k_split_w1<<<(2 * 128 * 64 + 255) / 256, 256>>>(w1r, w1o);
    k_split_w2<<<(128 * 64 + 255) / 256, 256>>>(w2r, w2o);

    // GEMM1 (launch slot ncu captures)
    k_gemm_f16<<<dim3(TILES, 2), 256, SMEMB>>>(xhp, w1hp, w1hp + 128 * 64, yhp, zp, 0);

    // CSR build
    k_detect<<<1, 256>>>((const int*)ei);
    k_zero_cnt<<<NB, 256>>>();
    k_count<<<EB, 256>>>(ei);
    k_scan1<<<NBLK_SCAN, 1024>>>();
    k_scan2<<<1, 128>>>();
    k_scan3<<<NBLK_SCAN, 1024>>>();
    k_fill<<<EB, 256>>>(ei);

    // layer 1 aggregation (fp16 gather, writes fp16 h image)
    k_agg1<<<AB, 256>>>(b1);

    // layer 2
    k_gemm_f16<<<dim3(TILES, 1), 256, SMEMB>>>(hhp, w2hp, w2hp, php, qp, 1);
    k_agg2<<<AB, 256>>>(b2, out);
}